// round 2
// baseline (speedup 1.0000x reference)
#include <cuda_runtime.h>
#include <math.h>

#define B_ 64
#define N_ 512
#define D_ 128
#define K_ 32
#define IN_ 256
#define M_ (B_ * N_)
#define EPS_ 1e-5f

// ---------------- device scratch ----------------
__device__ float g_xlin[M_ * D_];
__device__ float g_si[M_];
__device__ float g_sj[M_];
__device__ float g_ei[N_];
__device__ float g_ej[N_];
__device__ float g_nrm[N_];
__device__ int   g_topk[N_ * K_];
__device__ float g_agg[M_ * D_];
__device__ float g_h[M_ * D_];
__device__ float g_o1[M_ * IN_];
__device__ float g_o2[M_ * IN_];
// stats layout: [0]=agg sum(128) [128]=agg sq(128) [256]=h sum [384]=h sq
//               [512]=o1 sum(256) [768]=o1 sq [1024]=o2 sum [1280]=o2 sq
__device__ float g_red[1536];

// ---------------- zero stats ----------------
__global__ void k_zero() {
    int i = blockIdx.x * 256 + threadIdx.x;
    if (i < 1536) g_red[i] = 0.0f;
}

// ---------------- per-node: norm + emb attention parts ----------------
__global__ void k_pre(const float* __restrict__ emb,
                      const float* __restrict__ aei,
                      const float* __restrict__ aej) {
    int n = blockIdx.x;
    int t = threadIdx.x;  // 128
    float v = emb[n * D_ + t];
    float s2 = v * v, pi = v * aei[t], pj = v * aej[t];
    for (int o = 16; o > 0; o >>= 1) {
        s2 += __shfl_xor_sync(0xffffffffu, s2, o);
        pi += __shfl_xor_sync(0xffffffffu, pi, o);
        pj += __shfl_xor_sync(0xffffffffu, pj, o);
    }
    __shared__ float sh[3][4];
    int w = t >> 5, l = t & 31;
    if (l == 0) { sh[0][w] = s2; sh[1][w] = pi; sh[2][w] = pj; }
    __syncthreads();
    if (t == 0) {
        float a = 0, b = 0, c = 0;
        for (int q = 0; q < 4; q++) { a += sh[0][q]; b += sh[1][q]; c += sh[2][q]; }
        g_nrm[n] = sqrtf(a);
        g_ei[n] = b;
        g_ej[n] = c;
    }
}

// ---------------- cosine topk (one block per row) ----------------
__global__ void k_topk(const float* __restrict__ emb) {
    __shared__ float rme[D_];
    __shared__ float cosv[N_];
    __shared__ float bv[128];
    __shared__ int   bi[128];
    int i = blockIdx.x;
    int t = threadIdx.x;  // 128
    rme[t] = emb[i * D_ + t];
    __syncthreads();
    float inv_i = 1.0f / g_nrm[i];
    for (int j = t; j < N_; j += 128) {
        float dot = 0.0f;
        const float* ej = emb + j * D_;
        #pragma unroll 8
        for (int d = 0; d < D_; d++) dot += rme[d] * ej[d];
        cosv[j] = dot * inv_i / g_nrm[j];
    }
    __syncthreads();
    for (int k = 0; k < K_; k++) {
        float best = -2.0f; int besti = N_;
        for (int j = t; j < N_; j += 128) {
            float v = cosv[j];
            if (v > best) { best = v; besti = j; }
        }
        bv[t] = best; bi[t] = besti;
        __syncthreads();
        for (int s = 64; s > 0; s >>= 1) {
            if (t < s) {
                if (bv[t + s] > bv[t] || (bv[t + s] == bv[t] && bi[t + s] < bi[t])) {
                    bv[t] = bv[t + s]; bi[t] = bi[t + s];
                }
            }
            __syncthreads();
        }
        if (t == 0) { g_topk[i * K_ + k] = bi[0]; cosv[bi[0]] = -2.0f; }
        __syncthreads();
    }
}

// ---------------- x_lin = data @ lin_W ; s_i, s_j ----------------
__global__ __launch_bounds__(256) void k_xlin(const float* __restrict__ x,
                                              const float* __restrict__ W,
                                              const float* __restrict__ ai,
                                              const float* __restrict__ aj) {
    __shared__ float Wsh[64][128];
    __shared__ float Xsh[16][64];
    int t = threadIdx.x;
    int row0 = blockIdx.x * 16;
    int colg = t & 31, rowg = t >> 5;  // 32 col groups x 8 row groups (=warp id)
    int col0 = colg * 4;
    float acc[2][4] = {};
    for (int kk = 0; kk < 2; kk++) {
        for (int e = t; e < 64 * 128; e += 256)
            Wsh[e >> 7][e & 127] = W[(kk * 64 + (e >> 7)) * 128 + (e & 127)];
        for (int e = t; e < 16 * 64; e += 256)
            Xsh[e >> 6][e & 63] = x[(row0 + (e >> 6)) * 128 + kk * 64 + (e & 63)];
        __syncthreads();
        #pragma unroll
        for (int k = 0; k < 64; k++) {
            float4 w4 = *(float4*)&Wsh[k][col0];
            float xv0 = Xsh[rowg * 2 + 0][k];
            float xv1 = Xsh[rowg * 2 + 1][k];
            acc[0][0] += xv0 * w4.x; acc[0][1] += xv0 * w4.y;
            acc[0][2] += xv0 * w4.z; acc[0][3] += xv0 * w4.w;
            acc[1][0] += xv1 * w4.x; acc[1][1] += xv1 * w4.y;
            acc[1][2] += xv1 * w4.z; acc[1][3] += xv1 * w4.w;
        }
        __syncthreads();
    }
    float av_i[4], av_j[4];
    #pragma unroll
    for (int c = 0; c < 4; c++) { av_i[c] = ai[col0 + c]; av_j[c] = aj[col0 + c]; }
    #pragma unroll
    for (int r = 0; r < 2; r++) {
        int row = row0 + rowg * 2 + r;
        *(float4*)&g_xlin[row * D_ + col0] =
            make_float4(acc[r][0], acc[r][1], acc[r][2], acc[r][3]);
        float pi = 0, pj = 0;
        #pragma unroll
        for (int c = 0; c < 4; c++) { pi += acc[r][c] * av_i[c]; pj += acc[r][c] * av_j[c]; }
        for (int o = 16; o > 0; o >>= 1) {
            pi += __shfl_xor_sync(0xffffffffu, pi, o);
            pj += __shfl_xor_sync(0xffffffffu, pj, o);
        }
        if (colg == 0) {
            int n = row & (N_ - 1);
            g_si[row] = pi + g_ei[n];
            g_sj[row] = pj + g_ej[n];
        }
    }
}

// ---------------- attention aggregation + agg stats ----------------
__global__ __launch_bounds__(128) void k_attn() {
    __shared__ float alpha[33];
    __shared__ int   ssrc[33];
    int t = threadIdx.x;
    int m0 = blockIdx.x * 4;
    float ssum = 0.0f, ssq = 0.0f;
    for (int rr = 0; rr < 4; rr++) {
        int m = m0 + rr;
        int b = m >> 9;          // /N_
        int i = m & (N_ - 1);
        if (t < 32) {
            int src = g_topk[i * K_ + t];
            ssrc[t] = src;
            float sim = g_si[m];
            float v  = sim + g_sj[b * N_ + src];
            float lg = v > 0.0f ? v : 0.2f * v;
            bool valid = (src != i);
            if (!valid) lg = -1e30f;
            float vs  = sim + g_sj[m];
            float lgs = vs > 0.0f ? vs : 0.2f * vs;  // self loop
            float mx = lg;
            for (int o = 16; o > 0; o >>= 1)
                mx = fmaxf(mx, __shfl_xor_sync(0xffffffffu, mx, o));
            mx = fmaxf(mx, lgs);
            float e  = valid ? expf(lg - mx) : 0.0f;
            float es = expf(lgs - mx);
            float den = e;
            for (int o = 16; o > 0; o >>= 1)
                den += __shfl_xor_sync(0xffffffffu, den, o);
            den += es;
            alpha[t] = e / den;
            if (t == 0) { alpha[32] = es / den; ssrc[32] = i; }
        }
        __syncthreads();
        int bbase = b * N_;
        float acc = 0.0f;
        #pragma unroll
        for (int k = 0; k < 33; k++)
            acc += alpha[k] * g_xlin[(bbase + ssrc[k]) * D_ + t];
        g_agg[m * D_ + t] = acc;
        ssum += acc; ssq += acc * acc;
        __syncthreads();
    }
    atomicAdd(&g_red[t], ssum);
    atomicAdd(&g_red[D_ + t], ssq);
}

// ---------------- gcn = relu(bn(agg)); h = gcn*emb + h stats ----------------
__global__ __launch_bounds__(128) void k_h(const float* __restrict__ emb,
                                           const float* __restrict__ g0,
                                           const float* __restrict__ b0) {
    int d = threadIdx.x;
    int r0 = blockIdx.x * 64;
    const float invM = 1.0f / (float)M_;
    float mean = g_red[d] * invM;
    float var  = g_red[D_ + d] * invM - mean * mean;
    float sc = rsqrtf(var + EPS_) * g0[d];
    float sh = b0[d] - mean * sc;
    float ssum = 0.0f, ssq = 0.0f;
    for (int r = r0; r < r0 + 64; r++) {
        float a = g_agg[r * D_ + d];
        float gcn = fmaxf(a * sc + sh, 0.0f);
        float h = gcn * emb[(r & (N_ - 1)) * D_ + d];
        g_h[r * D_ + d] = h;
        ssum += h; ssq += h * h;
    }
    atomicAdd(&g_red[256 + d], ssum);
    atomicAdd(&g_red[384 + d], ssq);
}

// ---------------- MLP GEMM: out = relu(bn(X)) @ W ; accumulate out stats ----
// PASS=1: g_h[.,128] -> g_o1[.,256]   (stats in at 256, out at 512)
// PASS=2: g_o1[.,256] -> g_o2[.,256]  (stats in at 512, out at 1024)
// Scratch tensors are referenced as device globals INSIDE the kernel; only
// harness-provided pointers cross the host launch boundary.
template <int PASS>
__global__ __launch_bounds__(256) void k_mlp(const float* __restrict__ Wg,
                                             const float* __restrict__ gin,
                                             const float* __restrict__ bin) {
    constexpr int KD   = (PASS == 1) ? 128 : 256;
    constexpr int SIN  = (PASS == 1) ? 256 : 512;
    constexpr int SOUT = (PASS == 1) ? 512 : 1024;
    const float* __restrict__ Xg = (PASS == 1) ? g_h : g_o1;
    float* __restrict__ outg     = (PASS == 1) ? g_o1 : g_o2;

    __shared__ float Wsh[32][256];
    __shared__ float Xsh[16][32];
    __shared__ float nsc[256], nsh[256];
    __shared__ float sS[4][256];
    __shared__ float sQ[4][256];
    int t = threadIdx.x;
    int row0 = blockIdx.x * 16;
    const float invM = 1.0f / (float)M_;
    for (int f = t; f < KD; f += 256) {
        float mean = g_red[SIN + f] * invM;
        float var  = g_red[SIN + KD + f] * invM - mean * mean;
        float s = rsqrtf(var + EPS_) * gin[f];
        nsc[f] = s; nsh[f] = bin[f] - mean * s;
    }
    __syncthreads();
    int colg = t & 63, rowg = t >> 6;
    int col0 = colg * 4;
    float acc[4][4] = {};
    for (int kk = 0; kk < KD / 32; kk++) {
        for (int e = t; e < 32 * 256; e += 256)
            Wsh[e >> 8][e & 255] = Wg[(kk * 32 + (e >> 8)) * 256 + (e & 255)];
        {
            int e = t * 2;
            #pragma unroll
            for (int q = 0; q < 2; q++, e++) {
                int r = e >> 5, f = e & 31;
                int fc = kk * 32 + f;
                float v = Xg[(row0 + r) * KD + fc];
                Xsh[r][f] = fmaxf(v * nsc[fc] + nsh[fc], 0.0f);
            }
        }
        __syncthreads();
        #pragma unroll
        for (int k = 0; k < 32; k++) {
            float4 w4 = *(float4*)&Wsh[k][col0];
            #pragma unroll
            for (int r = 0; r < 4; r++) {
                float xv = Xsh[rowg * 4 + r][k];
                acc[r][0] += xv * w4.x; acc[r][1] += xv * w4.y;
                acc[r][2] += xv * w4.z; acc[r][3] += xv * w4.w;
            }
        }
        __syncthreads();
    }
    float cs[4] = {}, cq[4] = {};
    #pragma unroll
    for (int r = 0; r < 4; r++) {
        int row = row0 + rowg * 4 + r;
        *(float4*)&outg[row * 256 + col0] =
            make_float4(acc[r][0], acc[r][1], acc[r][2], acc[r][3]);
        #pragma unroll
        for (int c = 0; c < 4; c++) { cs[c] += acc[r][c]; cq[c] += acc[r][c] * acc[r][c]; }
    }
    #pragma unroll
    for (int c = 0; c < 4; c++) { sS[rowg][col0 + c] = cs[c]; sQ[rowg][col0 + c] = cq[c]; }
    __syncthreads();
    {
        int c = t;
        float s = sS[0][c] + sS[1][c] + sS[2][c] + sS[3][c];
        float q = sQ[0][c] + sQ[1][c] + sQ[2][c] + sQ[3][c];
        atomicAdd(&g_red[SOUT + c], s);
        atomicAdd(&g_red[SOUT + 256 + c], q);
    }
}

// ---------------- final: out = relu(bn(o2)) @ W3 + b3 ----------------
__global__ __launch_bounds__(256) void k_out(const float* __restrict__ W3,
                                             const float* __restrict__ b3,
                                             const float* __restrict__ g2,
                                             const float* __restrict__ b2v,
                                             float* __restrict__ out) {
    __shared__ float nsc[256], nsh[256], w[256];
    int t = threadIdx.x;
    const float invM = 1.0f / (float)M_;
    {
        float mean = g_red[1024 + t] * invM;
        float var  = g_red[1280 + t] * invM - mean * mean;
        float s = rsqrtf(var + EPS_) * g2[t];
        nsc[t] = s; nsh[t] = b2v[t] - mean * s; w[t] = W3[t];
    }
    __syncthreads();
    int warp = t >> 5, lane = t & 31;
    int m = blockIdx.x * 8 + warp;
    float acc = 0.0f;
    #pragma unroll
    for (int f = lane; f < 256; f += 32) {
        float v = g_o2[m * 256 + f];
        acc += fmaxf(v * nsc[f] + nsh[f], 0.0f) * w[f];
    }
    for (int o = 16; o > 0; o >>= 1)
        acc += __shfl_xor_sync(0xffffffffu, acc, o);
    if (lane == 0) out[m] = acc + b3[0];
}

// ---------------- launch ----------------
extern "C" void kernel_launch(void* const* d_in, const int* in_sizes, int n_in,
                              void* d_out, int out_size) {
    const float* data   = (const float*)d_in[0];
    const float* emb    = (const float*)d_in[1];
    const float* lin_W  = (const float*)d_in[2];
    const float* att_i  = (const float*)d_in[3];
    const float* att_j  = (const float*)d_in[4];
    const float* aem_i  = (const float*)d_in[5];
    const float* aem_j  = (const float*)d_in[6];
    // d_in[7] = gnn_bias : cancels exactly under BN
    const float* gnn_g  = (const float*)d_in[8];
    const float* gnn_b  = (const float*)d_in[9];
    const float* bno_g  = (const float*)d_in[10];
    const float* bno_b  = (const float*)d_in[11];
    const float* W1     = (const float*)d_in[12];
    // d_in[13] = b1 : cancels
    const float* bn1_g  = (const float*)d_in[14];
    const float* bn1_b  = (const float*)d_in[15];
    const float* W2     = (const float*)d_in[16];
    // d_in[17] = b2 : cancels
    const float* bn2_g  = (const float*)d_in[18];
    const float* bn2_b  = (const float*)d_in[19];
    const float* W3     = (const float*)d_in[20];
    const float* b3     = (const float*)d_in[21];
    float* out = (float*)d_out;

    k_zero<<<6, 256>>>();
    k_pre<<<N_, 128>>>(emb, aem_i, aem_j);
    k_topk<<<N_, 128>>>(emb);
    k_xlin<<<M_ / 16, 256>>>(data, lin_W, att_i, att_j);
    k_attn<<<M_ / 4, 128>>>();
    k_h<<<M_ / 64, 128>>>(emb, gnn_g, gnn_b);
    k_mlp<1><<<M_ / 16, 256>>>(W1, bno_g, bno_b);
    k_mlp<2><<<M_ / 16, 256>>>(W2, bn1_g, bn1_b);
    k_out<<<M_ / 8, 256>>>(W3, b3, bn2_g, bn2_b, out);
}

// round 3
// speedup vs baseline: 1.1767x; 1.1767x over previous
#include <cuda_runtime.h>
#include <math.h>

#define B_ 64
#define N_ 512
#define D_ 128
#define K_ 32
#define IN_ 256
#define M_ (B_ * N_)
#define EPS_ 1e-5f

// ---------------- device scratch ----------------
__device__ float g_xlin[M_ * D_];
__device__ float g_si[M_];
__device__ float g_sj[M_];
__device__ float g_ei[N_];
__device__ float g_ej[N_];
__device__ float g_nrm[N_];
__device__ int   g_topk[N_ * K_];
__device__ float g_agg[M_ * D_];
__device__ float g_h[M_ * D_];
__device__ float g_o1[M_ * IN_];
__device__ float g_o2[M_ * IN_];
// stats layout: [0]=agg sum(128) [128]=agg sq(128) [256]=h sum [384]=h sq
//               [512]=o1 sum(256) [768]=o1 sq [1024]=o2 sum [1280]=o2 sq
__device__ float g_red[1536];

// ---------------- packed f32x2 helpers ----------------
__device__ __forceinline__ unsigned long long pk2(float x) {
    unsigned long long r;
    asm("mov.b64 %0, {%1, %2};" : "=l"(r) : "f"(x), "f"(x));
    return r;
}
__device__ __forceinline__ void fma2(unsigned long long& d,
                                     unsigned long long a,
                                     unsigned long long b) {
    asm("fma.rn.f32x2 %0, %1, %2, %0;" : "+l"(d) : "l"(a), "l"(b));
}
__device__ __forceinline__ float2 upk(unsigned long long v) {
    float2 f;
    asm("mov.b64 {%0, %1}, %2;" : "=f"(f.x), "=f"(f.y) : "l"(v));
    return f;
}

// ---------------- zero stats ----------------
__global__ void k_zero() {
    int i = blockIdx.x * 256 + threadIdx.x;
    if (i < 1536) g_red[i] = 0.0f;
}

// ---------------- per-node: norm + emb attention parts ----------------
__global__ void k_pre(const float* __restrict__ emb,
                      const float* __restrict__ aei,
                      const float* __restrict__ aej) {
    int n = blockIdx.x;
    int t = threadIdx.x;  // 128
    float v = emb[n * D_ + t];
    float s2 = v * v, pi = v * aei[t], pj = v * aej[t];
    for (int o = 16; o > 0; o >>= 1) {
        s2 += __shfl_xor_sync(0xffffffffu, s2, o);
        pi += __shfl_xor_sync(0xffffffffu, pi, o);
        pj += __shfl_xor_sync(0xffffffffu, pj, o);
    }
    __shared__ float sh[3][4];
    int w = t >> 5, l = t & 31;
    if (l == 0) { sh[0][w] = s2; sh[1][w] = pi; sh[2][w] = pj; }
    __syncthreads();
    if (t == 0) {
        float a = 0, b = 0, c = 0;
        for (int q = 0; q < 4; q++) { a += sh[0][q]; b += sh[1][q]; c += sh[2][q]; }
        g_nrm[n] = sqrtf(a);
        g_ei[n] = b;
        g_ej[n] = c;
    }
}

// ---------------- cosine topk (one block per row) ----------------
__global__ void k_topk(const float* __restrict__ emb) {
    __shared__ float rme[D_];
    __shared__ float cosv[N_];
    __shared__ float bv[128];
    __shared__ int   bi[128];
    int i = blockIdx.x;
    int t = threadIdx.x;  // 128
    rme[t] = emb[i * D_ + t];
    __syncthreads();
    float inv_i = 1.0f / g_nrm[i];
    for (int j = t; j < N_; j += 128) {
        float dot = 0.0f;
        const float* ej = emb + j * D_;
        #pragma unroll 8
        for (int d = 0; d < D_; d++) dot += rme[d] * ej[d];
        cosv[j] = dot * inv_i / g_nrm[j];
    }
    __syncthreads();
    for (int k = 0; k < K_; k++) {
        float best = -2.0f; int besti = N_;
        for (int j = t; j < N_; j += 128) {
            float v = cosv[j];
            if (v > best) { best = v; besti = j; }
        }
        bv[t] = best; bi[t] = besti;
        __syncthreads();
        for (int s = 64; s > 0; s >>= 1) {
            if (t < s) {
                if (bv[t + s] > bv[t] || (bv[t + s] == bv[t] && bi[t + s] < bi[t])) {
                    bv[t] = bv[t + s]; bi[t] = bi[t + s];
                }
            }
            __syncthreads();
        }
        if (t == 0) { g_topk[i * K_ + k] = bi[0]; cosv[bi[0]] = -2.0f; }
        __syncthreads();
    }
}

// ---------------- x_lin = data @ lin_W ; s_i, s_j ----------------
// 64x128 block tile, 256 threads, 4x8 micro-tile via packed f32x2 FMA.
// Thread cols: {colg*4..+3} and {64+colg*4..+3}  (conflict-free LDS.128)
__global__ __launch_bounds__(256) void k_xlin(const float* __restrict__ x,
                                              const float* __restrict__ W,
                                              const float* __restrict__ ai,
                                              const float* __restrict__ aj) {
    __shared__ float Wsh[16 * 128];
    __shared__ float Xsh[16][64];
    int t = threadIdx.x;
    int row0 = blockIdx.x * 64;
    int rowg = t >> 4, colg = t & 15;
    int xr = t >> 2, xk4 = (t & 3) * 4;
    unsigned long long acc[4][4] = {};
    for (int kk = 0; kk < 8; kk++) {
        *(float4*)&Wsh[t * 4] = *(const float4*)&W[kk * 2048 + t * 4];
        *(float4*)&Wsh[1024 + t * 4] = *(const float4*)&W[kk * 2048 + 1024 + t * 4];
        float4 v = *(const float4*)&x[(row0 + xr) * 128 + kk * 16 + xk4];
        Xsh[xk4 + 0][xr] = v.x; Xsh[xk4 + 1][xr] = v.y;
        Xsh[xk4 + 2][xr] = v.z; Xsh[xk4 + 3][xr] = v.w;
        __syncthreads();
        #pragma unroll
        for (int k = 0; k < 16; k++) {
            float4 a4 = *(float4*)&Xsh[k][rowg * 4];
            ulonglong2 b0 = *(ulonglong2*)&Wsh[k * 128 + colg * 4];
            ulonglong2 b1 = *(ulonglong2*)&Wsh[k * 128 + 64 + colg * 4];
            unsigned long long aa0 = pk2(a4.x), aa1 = pk2(a4.y);
            unsigned long long aa2 = pk2(a4.z), aa3 = pk2(a4.w);
            fma2(acc[0][0], aa0, b0.x); fma2(acc[0][1], aa0, b0.y);
            fma2(acc[0][2], aa0, b1.x); fma2(acc[0][3], aa0, b1.y);
            fma2(acc[1][0], aa1, b0.x); fma2(acc[1][1], aa1, b0.y);
            fma2(acc[1][2], aa1, b1.x); fma2(acc[1][3], aa1, b1.y);
            fma2(acc[2][0], aa2, b0.x); fma2(acc[2][1], aa2, b0.y);
            fma2(acc[2][2], aa2, b1.x); fma2(acc[2][3], aa2, b1.y);
            fma2(acc[3][0], aa3, b0.x); fma2(acc[3][1], aa3, b0.y);
            fma2(acc[3][2], aa3, b1.x); fma2(acc[3][3], aa3, b1.y);
        }
        __syncthreads();
    }
    float avi[8], avj[8];
    #pragma unroll
    for (int c = 0; c < 4; c++) {
        avi[c]     = ai[colg * 4 + c];      avj[c]     = aj[colg * 4 + c];
        avi[4 + c] = ai[64 + colg * 4 + c]; avj[4 + c] = aj[64 + colg * 4 + c];
    }
    #pragma unroll
    for (int r = 0; r < 4; r++) {
        int row = row0 + rowg * 4 + r;
        *(ulonglong2*)&g_xlin[row * 128 + colg * 4] =
            make_ulonglong2(acc[r][0], acc[r][1]);
        *(ulonglong2*)&g_xlin[row * 128 + 64 + colg * 4] =
            make_ulonglong2(acc[r][2], acc[r][3]);
        float pi = 0.0f, pj = 0.0f;
        #pragma unroll
        for (int cp = 0; cp < 4; cp++) {
            float2 f = upk(acc[r][cp]);
            pi += f.x * avi[cp * 2] + f.y * avi[cp * 2 + 1];
            pj += f.x * avj[cp * 2] + f.y * avj[cp * 2 + 1];
        }
        for (int o = 8; o > 0; o >>= 1) {
            pi += __shfl_xor_sync(0xffffffffu, pi, o);
            pj += __shfl_xor_sync(0xffffffffu, pj, o);
        }
        if (colg == 0) {
            int n = row & (N_ - 1);
            g_si[row] = pi + g_ei[n];
            g_sj[row] = pj + g_ej[n];
        }
    }
}

// ---------------- attention aggregation + agg stats ----------------
__global__ __launch_bounds__(128) void k_attn() {
    __shared__ float alpha[33];
    __shared__ int   ssrc[33];
    int t = threadIdx.x;
    int m0 = blockIdx.x * 4;
    float ssum = 0.0f, ssq = 0.0f;
    for (int rr = 0; rr < 4; rr++) {
        int m = m0 + rr;
        int b = m >> 9;          // /N_
        int i = m & (N_ - 1);
        if (t < 32) {
            int src = g_topk[i * K_ + t];
            ssrc[t] = src;
            float sim = g_si[m];
            float v  = sim + g_sj[b * N_ + src];
            float lg = v > 0.0f ? v : 0.2f * v;
            bool valid = (src != i);
            if (!valid) lg = -1e30f;
            float vs  = sim + g_sj[m];
            float lgs = vs > 0.0f ? vs : 0.2f * vs;  // self loop
            float mx = lg;
            for (int o = 16; o > 0; o >>= 1)
                mx = fmaxf(mx, __shfl_xor_sync(0xffffffffu, mx, o));
            mx = fmaxf(mx, lgs);
            float e  = valid ? expf(lg - mx) : 0.0f;
            float es = expf(lgs - mx);
            float den = e;
            for (int o = 16; o > 0; o >>= 1)
                den += __shfl_xor_sync(0xffffffffu, den, o);
            den += es;
            alpha[t] = e / den;
            if (t == 0) { alpha[32] = es / den; ssrc[32] = i; }
        }
        __syncthreads();
        int bbase = b * N_;
        float acc = 0.0f;
        #pragma unroll
        for (int k = 0; k < 33; k++)
            acc += alpha[k] * g_xlin[(bbase + ssrc[k]) * D_ + t];
        g_agg[m * D_ + t] = acc;
        ssum += acc; ssq += acc * acc;
        __syncthreads();
    }
    atomicAdd(&g_red[t], ssum);
    atomicAdd(&g_red[D_ + t], ssq);
}

// ---------------- gcn = relu(bn(agg)); h = gcn*emb + h stats ----------------
__global__ __launch_bounds__(128) void k_h(const float* __restrict__ emb,
                                           const float* __restrict__ g0,
                                           const float* __restrict__ b0) {
    int d = threadIdx.x;
    int r0 = blockIdx.x * 64;
    const float invM = 1.0f / (float)M_;
    float mean = g_red[d] * invM;
    float var  = g_red[D_ + d] * invM - mean * mean;
    float sc = rsqrtf(var + EPS_) * g0[d];
    float sh = b0[d] - mean * sc;
    float ssum = 0.0f, ssq = 0.0f;
    for (int r = r0; r < r0 + 64; r++) {
        float a = g_agg[r * D_ + d];
        float gcn = fmaxf(a * sc + sh, 0.0f);
        float h = gcn * emb[(r & (N_ - 1)) * D_ + d];
        g_h[r * D_ + d] = h;
        ssum += h; ssq += h * h;
    }
    atomicAdd(&g_red[256 + d], ssum);
    atomicAdd(&g_red[384 + d], ssq);
}

// ---------------- MLP GEMM: out = relu(bn(X)) @ W ; accumulate out stats ----
// KD=128: g_h -> g_o1 (stats 256 -> 512); KD=256: g_o1 -> g_o2 (512 -> 1024)
// 64x128 block tile (grid.y picks col half), 4x8 micro-tile, packed f32x2.
template <int KD>
__global__ __launch_bounds__(256) void k_mlp(const float* __restrict__ Wg,
                                             const float* __restrict__ gin,
                                             const float* __restrict__ bin) {
    constexpr int SIN  = (KD == 128) ? 256 : 512;
    constexpr int SOUT = (KD == 128) ? 512 : 1024;
    const float* __restrict__ Xg = (KD == 128) ? g_h : g_o1;
    float* __restrict__ outg     = (KD == 128) ? g_o1 : g_o2;

    __shared__ float Wsh[16 * 128];
    __shared__ float Xsh[16][64];
    __shared__ float nsc[KD], nsh[KD];
    __shared__ float sred[16 * 128];

    int t = threadIdx.x;
    int row0 = blockIdx.x * 64;
    int cb = blockIdx.y * 128;
    const float invM = 1.0f / (float)M_;
    for (int f = t; f < KD; f += 256) {
        float mean = g_red[SIN + f] * invM;
        float var  = g_red[SIN + KD + f] * invM - mean * mean;
        float s = rsqrtf(var + EPS_) * gin[f];
        nsc[f] = s; nsh[f] = bin[f] - mean * s;
    }
    __syncthreads();

    int rowg = t >> 4, colg = t & 15;
    int xr = t >> 2, xk4 = (t & 3) * 4;
    unsigned long long acc[4][4] = {};
    for (int kk = 0; kk < KD / 16; kk++) {
        {
            int e = t * 4;
            #pragma unroll
            for (int q = 0; q < 2; q++, e += 1024) {
                int k = e >> 7, c = e & 127;
                *(float4*)&Wsh[e] = *(const float4*)&Wg[(kk * 16 + k) * 256 + cb + c];
            }
        }
        {
            float4 v = *(const float4*)&Xg[(row0 + xr) * KD + kk * 16 + xk4];
            int fc = kk * 16 + xk4;
            Xsh[xk4 + 0][xr] = fmaxf(v.x * nsc[fc + 0] + nsh[fc + 0], 0.0f);
            Xsh[xk4 + 1][xr] = fmaxf(v.y * nsc[fc + 1] + nsh[fc + 1], 0.0f);
            Xsh[xk4 + 2][xr] = fmaxf(v.z * nsc[fc + 2] + nsh[fc + 2], 0.0f);
            Xsh[xk4 + 3][xr] = fmaxf(v.w * nsc[fc + 3] + nsh[fc + 3], 0.0f);
        }
        __syncthreads();
        #pragma unroll
        for (int k = 0; k < 16; k++) {
            float4 a4 = *(float4*)&Xsh[k][rowg * 4];
            ulonglong2 b0 = *(ulonglong2*)&Wsh[k * 128 + colg * 4];
            ulonglong2 b1 = *(ulonglong2*)&Wsh[k * 128 + 64 + colg * 4];
            unsigned long long aa0 = pk2(a4.x), aa1 = pk2(a4.y);
            unsigned long long aa2 = pk2(a4.z), aa3 = pk2(a4.w);
            fma2(acc[0][0], aa0, b0.x); fma2(acc[0][1], aa0, b0.y);
            fma2(acc[0][2], aa0, b1.x); fma2(acc[0][3], aa0, b1.y);
            fma2(acc[1][0], aa1, b0.x); fma2(acc[1][1], aa1, b0.y);
            fma2(acc[1][2], aa1, b1.x); fma2(acc[1][3], aa1, b1.y);
            fma2(acc[2][0], aa2, b0.x); fma2(acc[2][1], aa2, b0.y);
            fma2(acc[2][2], aa2, b1.x); fma2(acc[2][3], aa2, b1.y);
            fma2(acc[3][0], aa3, b0.x); fma2(acc[3][1], aa3, b0.y);
            fma2(acc[3][2], aa3, b1.x); fma2(acc[3][3], aa3, b1.y);
        }
        __syncthreads();
    }
    float cs[8] = {}, cq[8] = {};
    #pragma unroll
    for (int r = 0; r < 4; r++) {
        int row = row0 + rowg * 4 + r;
        *(ulonglong2*)&outg[row * 256 + cb + colg * 4] =
            make_ulonglong2(acc[r][0], acc[r][1]);
        *(ulonglong2*)&outg[row * 256 + cb + 64 + colg * 4] =
            make_ulonglong2(acc[r][2], acc[r][3]);
        #pragma unroll
        for (int cp = 0; cp < 4; cp++) {
            float2 f = upk(acc[r][cp]);
            cs[cp * 2] += f.x;        cs[cp * 2 + 1] += f.y;
            cq[cp * 2] += f.x * f.x;  cq[cp * 2 + 1] += f.y * f.y;
        }
    }
    // cs[0..3] -> local cols colg*4..+3 ; cs[4..7] -> 64+colg*4..+3
    #pragma unroll
    for (int c = 0; c < 4; c++) {
        sred[rowg * 128 + colg * 4 + c]      = cs[c];
        sred[rowg * 128 + 64 + colg * 4 + c] = cs[4 + c];
    }
    __syncthreads();
    if (t < 128) {
        float s = 0.0f;
        #pragma unroll
        for (int g = 0; g < 16; g++) s += sred[g * 128 + t];
        atomicAdd(&g_red[SOUT + cb + t], s);
    }
    __syncthreads();
    #pragma unroll
    for (int c = 0; c < 4; c++) {
        sred[rowg * 128 + colg * 4 + c]      = cq[c];
        sred[rowg * 128 + 64 + colg * 4 + c] = cq[4 + c];
    }
    __syncthreads();
    if (t < 128) {
        float s = 0.0f;
        #pragma unroll
        for (int g = 0; g < 16; g++) s += sred[g * 128 + t];
        atomicAdd(&g_red[SOUT + 256 + cb + t], s);
    }
}

// ---------------- final: out = relu(bn(o2)) @ W3 + b3 ----------------
__global__ __launch_bounds__(256) void k_out(const float* __restrict__ W3,
                                             const float* __restrict__ b3,
                                             const float* __restrict__ g2,
                                             const float* __restrict__ b2v,
                                             float* __restrict__ out) {
    __shared__ float nsc[256], nsh[256], w[256];
    int t = threadIdx.x;
    const float invM = 1.0f / (float)M_;
    {
        float mean = g_red[1024 + t] * invM;
        float var  = g_red[1280 + t] * invM - mean * mean;
        float s = rsqrtf(var + EPS_) * g2[t];
        nsc[t] = s; nsh[t] = b2v[t] - mean * s; w[t] = W3[t];
    }
    __syncthreads();
    int warp = t >> 5, lane = t & 31;
    int m = blockIdx.x * 8 + warp;
    float acc = 0.0f;
    #pragma unroll
    for (int f = lane; f < 256; f += 32) {
        float v = g_o2[m * 256 + f];
        acc += fmaxf(v * nsc[f] + nsh[f], 0.0f) * w[f];
    }
    for (int o = 16; o > 0; o >>= 1)
        acc += __shfl_xor_sync(0xffffffffu, acc, o);
    if (lane == 0) out[m] = acc + b3[0];
}

// ---------------- launch ----------------
extern "C" void kernel_launch(void* const* d_in, const int* in_sizes, int n_in,
                              void* d_out, int out_size) {
    const float* data   = (const float*)d_in[0];
    const float* emb    = (const float*)d_in[1];
    const float* lin_W  = (const float*)d_in[2];
    const float* att_i  = (const float*)d_in[3];
    const float* att_j  = (const float*)d_in[4];
    const float* aem_i  = (const float*)d_in[5];
    const float* aem_j  = (const float*)d_in[6];
    // d_in[7] = gnn_bias : cancels exactly under BN
    const float* gnn_g  = (const float*)d_in[8];
    const float* gnn_b  = (const float*)d_in[9];
    const float* bno_g  = (const float*)d_in[10];
    const float* bno_b  = (const float*)d_in[11];
    const float* W1     = (const float*)d_in[12];
    // d_in[13] = b1 : cancels
    const float* bn1_g  = (const float*)d_in[14];
    const float* bn1_b  = (const float*)d_in[15];
    const float* W2     = (const float*)d_in[16];
    // d_in[17] = b2 : cancels
    const float* bn2_g  = (const float*)d_in[18];
    const float* bn2_b  = (const float*)d_in[19];
    const float* W3     = (const float*)d_in[20];
    const float* b3     = (const float*)d_in[21];
    float* out = (float*)d_out;

    k_zero<<<6, 256>>>();
    k_pre<<<N_, 128>>>(emb, aem_i, aem_j);
    k_topk<<<N_, 128>>>(emb);
    k_xlin<<<M_ / 64, 256>>>(data, lin_W, att_i, att_j);
    k_attn<<<M_ / 4, 128>>>();
    k_h<<<M_ / 64, 128>>>(emb, gnn_g, gnn_b);
    k_mlp<128><<<dim3(M_ / 64, 2), 256>>>(W1, bno_g, bno_b);
    k_mlp<256><<<dim3(M_ / 64, 2), 256>>>(W2, bn1_g, bn1_b);
    k_out<<<M_ / 8, 256>>>(W3, b3, bn2_g, bn2_b, out);
}

// round 5
// speedup vs baseline: 1.5564x; 1.3227x over previous
#include <cuda_runtime.h>
#include <cuda_bf16.h>
#include <math.h>
#include <stdint.h>

#define B_ 64
#define N_ 512
#define D_ 128
#define K_ 32
#define M_ (B_ * N_)
#define EPS_ 1e-5f

typedef unsigned long long ull;
typedef unsigned short ushort_t;

// ---------------- device scratch ----------------
__device__ float g_xlin[M_ * D_];
__device__ float g_si[M_];
__device__ float g_sj[M_];
__device__ float g_ei[N_];
__device__ float g_ej[N_];
__device__ float g_nrm[N_];
__device__ int   g_topk[N_ * K_];
__device__ float g_agg[M_ * D_];
__device__ float g_h[M_ * D_];
__device__ float g_o1[M_ * 256];
__device__ float g_o2[M_ * 256];
// W images: [n][k] row-major bf16, hi/lo split
__device__ __nv_bfloat16 g_Wh0[128 * 128], g_Wl0[128 * 128];
__device__ __nv_bfloat16 g_Wh1[256 * 128], g_Wl1[256 * 128];
__device__ __nv_bfloat16 g_Wh2[256 * 256], g_Wl2[256 * 256];
// stats: [0]=agg sum(128) [128]=agg sq [256]=h sum [384]=h sq
//        [512]=o1 sum(256) [768]=o1 sq [1024]=o2 sum [1280]=o2 sq
__device__ float g_red[1536];

// ---------------- helpers ----------------
__device__ __forceinline__ uint32_t smem_to_u32(const void* p) {
    uint32_t a;
    asm("{ .reg .u64 t; cvta.to.shared.u64 t, %1; cvt.u32.u64 %0, t; }"
        : "=r"(a) : "l"(p));
    return a;
}
__device__ __forceinline__ ushort_t bf_hi(float f, ushort_t& lo) {
    __nv_bfloat16 h = __float2bfloat16(f);
    float r = f - __bfloat162float(h);
    lo = __bfloat16_as_ushort(__float2bfloat16(r));
    return __bfloat16_as_ushort(h);
}
__device__ __forceinline__ ull pack4(ushort_t a, ushort_t b, ushort_t c, ushort_t d) {
    return (ull)a | ((ull)b << 16) | ((ull)c << 32) | ((ull)d << 48);
}
#define LDSM_X4(r0, r1, r2, r3, addr) \
    asm volatile("ldmatrix.sync.aligned.m8n8.x4.shared.b16 {%0,%1,%2,%3}, [%4];" \
                 : "=r"(r0), "=r"(r1), "=r"(r2), "=r"(r3) : "r"(addr))
#define MMA(dd, aa, b0v, b1v) \
    asm volatile("mma.sync.aligned.m16n8k16.row.col.f32.bf16.bf16.f32 " \
                 "{%0,%1,%2,%3}, {%4,%5,%6,%7}, {%8,%9}, {%0,%1,%2,%3};" \
                 : "+f"((dd)[0]), "+f"((dd)[1]), "+f"((dd)[2]), "+f"((dd)[3]) \
                 : "r"((aa)[0]), "r"((aa)[1]), "r"((aa)[2]), "r"((aa)[3]), \
                   "r"(b0v), "r"(b1v))

// ---------------- zero stats ----------------
__global__ void k_zero() {
    int i = blockIdx.x * 256 + threadIdx.x;
    if (i < 1536) g_red[i] = 0.0f;
}

// ---------------- W prep: transpose + bf16 split into [n][k] images ---------
__global__ __launch_bounds__(1024) void k_prepW(const float* __restrict__ linW,
                                                const float* __restrict__ W1,
                                                const float* __restrict__ W2) {
    int id = blockIdx.x * 1024 + threadIdx.x;  // 112*1024 = 114688
    if (id < 16384) {
        int n = id >> 7, k = id & 127;
        ushort_t lo; ushort_t hi = bf_hi(linW[k * 128 + n], lo);
        g_Wh0[n * 128 + k] = __ushort_as_bfloat16(hi);
        g_Wl0[n * 128 + k] = __ushort_as_bfloat16(lo);
    } else if (id < 49152) {
        int e = id - 16384;
        int n = e >> 7, k = e & 127;
        ushort_t lo; ushort_t hi = bf_hi(W1[k * 256 + n], lo);
        g_Wh1[n * 128 + k] = __ushort_as_bfloat16(hi);
        g_Wl1[n * 128 + k] = __ushort_as_bfloat16(lo);
    } else {
        int e = id - 49152;
        int n = e >> 8, k = e & 255;
        ushort_t lo; ushort_t hi = bf_hi(W2[k * 256 + n], lo);
        g_Wh2[n * 256 + k] = __ushort_as_bfloat16(hi);
        g_Wl2[n * 256 + k] = __ushort_as_bfloat16(lo);
    }
}

// ---------------- per-node: norm + emb attention parts ----------------
__global__ void k_pre(const float* __restrict__ emb,
                      const float* __restrict__ aei,
                      const float* __restrict__ aej) {
    int n = blockIdx.x;
    int t = threadIdx.x;  // 128
    float v = emb[n * D_ + t];
    float s2 = v * v, pi = v * aei[t], pj = v * aej[t];
    for (int o = 16; o > 0; o >>= 1) {
        s2 += __shfl_xor_sync(0xffffffffu, s2, o);
        pi += __shfl_xor_sync(0xffffffffu, pi, o);
        pj += __shfl_xor_sync(0xffffffffu, pj, o);
    }
    __shared__ float sh[3][4];
    int w = t >> 5, l = t & 31;
    if (l == 0) { sh[0][w] = s2; sh[1][w] = pi; sh[2][w] = pj; }
    __syncthreads();
    if (t == 0) {
        float a = 0, b = 0, c = 0;
        for (int q = 0; q < 4; q++) { a += sh[0][q]; b += sh[1][q]; c += sh[2][q]; }
        g_nrm[n] = sqrtf(a);
        g_ei[n] = b;
        g_ej[n] = c;
    }
}

// ---------------- cosine topk (one block per row) ----------------
__global__ void k_topk(const float* __restrict__ emb) {
    __shared__ float rme[D_];
    __shared__ float cosv[N_];
    __shared__ float bv[128];
    __shared__ int   bi[128];
    int i = blockIdx.x;
    int t = threadIdx.x;  // 128
    rme[t] = emb[i * D_ + t];
    __syncthreads();
    float inv_i = 1.0f / g_nrm[i];
    for (int j = t; j < N_; j += 128) {
        float dot = 0.0f;
        const float* ej = emb + j * D_;
        #pragma unroll 8
        for (int d = 0; d < D_; d++) dot += rme[d] * ej[d];
        cosv[j] = dot * inv_i / g_nrm[j];
    }
    __syncthreads();
    for (int k = 0; k < K_; k++) {
        float best = -2.0f; int besti = N_;
        for (int j = t; j < N_; j += 128) {
            float v = cosv[j];
            if (v > best) { best = v; besti = j; }
        }
        bv[t] = best; bi[t] = besti;
        __syncthreads();
        for (int s = 64; s > 0; s >>= 1) {
            if (t < s) {
                if (bv[t + s] > bv[t] || (bv[t + s] == bv[t] && bi[t + s] < bi[t])) {
                    bv[t] = bv[t + s]; bi[t] = bi[t + s];
                }
            }
            __syncthreads();
        }
        if (t == 0) { g_topk[i * K_ + k] = bi[0]; cosv[bi[0]] = -2.0f; }
        __syncthreads();
    }
}

// ---------------- unified HMMA GEMM (3-term bf16 split) ----------------
// PASS 0: g_xlin = data @ linW          (KD=128, NOUT=128, raw X, no stats)
// PASS 1: g_o1 = relu(bn(g_h)) @ W1    (KD=128, NOUT=256, stats 256->512)
// PASS 2: g_o2 = relu(bn(g_o1)) @ W2   (KD=256, NOUT=256, stats 512->1024)
// Block tile 128x128, 8 warps (4 m-rows x 2 n-cols), warp tile 32x64.
template <int PASS>
__global__ __launch_bounds__(256) void k_gemm(const float* __restrict__ Xext,
                                              const float* __restrict__ gin,
                                              const float* __restrict__ bin) {
    constexpr int KD   = (PASS == 2) ? 256 : 128;
    constexpr int OSTR = (PASS == 0) ? 128 : 256;
    constexpr int SIN  = (PASS == 1) ? 256 : 512;
    constexpr int SOUT = (PASS == 1) ? 512 : 1024;

    __shared__ __align__(16) __nv_bfloat16 Xh[128 * 40];
    __shared__ __align__(16) __nv_bfloat16 Xl[128 * 40];
    __shared__ __align__(16) __nv_bfloat16 Wh[128 * 40];
    __shared__ __align__(16) __nv_bfloat16 Wl[128 * 40];
    __shared__ float nsc[256], nsh[256];
    __shared__ float sbS[4][128], sbQ[4][128];

    const float* __restrict__ Xg =
        (PASS == 0) ? Xext : ((PASS == 1) ? g_h : g_o1);
    float* __restrict__ outg =
        (PASS == 0) ? g_xlin : ((PASS == 1) ? g_o1 : g_o2);
    const __nv_bfloat16* Wgh = (PASS == 0) ? g_Wh0 : ((PASS == 1) ? g_Wh1 : g_Wh2);
    const __nv_bfloat16* Wgl = (PASS == 0) ? g_Wl0 : ((PASS == 1) ? g_Wl1 : g_Wl2);

    int t = threadIdx.x, l = t & 31, w = t >> 5;
    int wr = w >> 1, wc = w & 1;
    int row0 = blockIdx.x * 128;
    int nb = blockIdx.y;
    const __nv_bfloat16* WghB = Wgh + nb * 128 * KD;
    const __nv_bfloat16* WglB = Wgl + nb * 128 * KD;

    if (PASS != 0) {
        const float invM = 1.0f / (float)M_;
        if (t < KD) {
            float mean = g_red[SIN + t] * invM;
            float var  = g_red[SIN + KD + t] * invM - mean * mean;
            float s = rsqrtf(var + EPS_) * gin[t];
            nsc[t] = s; nsh[t] = bin[t] - mean * s;
        }
        __syncthreads();
    }

    float d[2][8][4] = {};
    uint32_t xh_b = smem_to_u32(Xh), xl_b = smem_to_u32(Xl);
    uint32_t wh_b = smem_to_u32(Wh), wl_b = smem_to_u32(Wl);

    for (int kb = 0; kb < KD; kb += 32) {
        // ---- X tile fill (optional BN+relu, bf16 split) ----
        #pragma unroll
        for (int v = t; v < 1024; v += 256) {
            int r = v >> 3, k4 = (v & 7) * 4;
            float4 x4 = *(const float4*)&Xg[(row0 + r) * KD + kb + k4];
            float f0, f1, f2, f3;
            if (PASS == 0) {
                f0 = x4.x; f1 = x4.y; f2 = x4.z; f3 = x4.w;
            } else {
                int fc = kb + k4;
                f0 = fmaxf(x4.x * nsc[fc + 0] + nsh[fc + 0], 0.0f);
                f1 = fmaxf(x4.y * nsc[fc + 1] + nsh[fc + 1], 0.0f);
                f2 = fmaxf(x4.z * nsc[fc + 2] + nsh[fc + 2], 0.0f);
                f3 = fmaxf(x4.w * nsc[fc + 3] + nsh[fc + 3], 0.0f);
            }
            ushort_t l0, l1, l2, l3;
            ushort_t h0 = bf_hi(f0, l0), h1 = bf_hi(f1, l1);
            ushort_t h2 = bf_hi(f2, l2), h3 = bf_hi(f3, l3);
            *(ull*)(&Xh[r * 40 + k4]) = pack4(h0, h1, h2, h3);
            *(ull*)(&Xl[r * 40 + k4]) = pack4(l0, l1, l2, l3);
        }
        // ---- W tile copy (bf16 images, float4 = 8 bf16) ----
        #pragma unroll
        for (int v = t; v < 512; v += 256) {
            int n = v >> 2, k8 = (v & 3) * 8;
            *(float4*)&Wh[n * 40 + k8] = *(const float4*)&WghB[n * KD + kb + k8];
            *(float4*)&Wl[n * 40 + k8] = *(const float4*)&WglB[n * KD + kb + k8];
        }
        __syncthreads();
        #pragma unroll
        for (int ks = 0; ks < 32; ks += 16) {
            uint32_t ah[2][4], al[2][4];
            uint32_t arow = (uint32_t)(l & 15);
            uint32_t akoff = (uint32_t)((l >> 4) << 3);
            #pragma unroll
            for (int mt = 0; mt < 2; mt++) {
                uint32_t off = ((wr * 32 + mt * 16 + arow) * 40 + ks + akoff) * 2;
                LDSM_X4(ah[mt][0], ah[mt][1], ah[mt][2], ah[mt][3], xh_b + off);
                LDSM_X4(al[mt][0], al[mt][1], al[mt][2], al[mt][3], xl_b + off);
            }
            uint32_t brow = (uint32_t)(((l >> 4) << 3) + (l & 7));
            uint32_t bkoff = (uint32_t)(((l >> 3) & 1) << 3);
            #pragma unroll
            for (int g = 0; g < 4; g++) {
                uint32_t off = ((wc * 64 + g * 16 + brow) * 40 + ks + bkoff) * 2;
                uint32_t bh[4], bl[4];
                LDSM_X4(bh[0], bh[1], bh[2], bh[3], wh_b + off);
                LDSM_X4(bl[0], bl[1], bl[2], bl[3], wl_b + off);
                #pragma unroll
                for (int mt = 0; mt < 2; mt++) {
                    MMA(d[mt][2 * g],     ah[mt], bh[0], bh[1]);
                    MMA(d[mt][2 * g],     ah[mt], bl[0], bl[1]);
                    MMA(d[mt][2 * g],     al[mt], bh[0], bh[1]);
                    MMA(d[mt][2 * g + 1], ah[mt], bh[2], bh[3]);
                    MMA(d[mt][2 * g + 1], ah[mt], bl[2], bl[3]);
                    MMA(d[mt][2 * g + 1], al[mt], bh[2], bh[3]);
                }
            }
        }
        __syncthreads();
    }

    // ---- store + fused column stats ----
    int rbase = row0 + wr * 32 + (l >> 2);
    int cbase = nb * 128 + wc * 64 + (l & 3) * 2;
    #pragma unroll
    for (int mt = 0; mt < 2; mt++) {
        #pragma unroll
        for (int nt = 0; nt < 8; nt++) {
            int col = cbase + nt * 8;
            *(float2*)&outg[(rbase + mt * 16) * OSTR + col] =
                make_float2(d[mt][nt][0], d[mt][nt][1]);
            *(float2*)&outg[(rbase + mt * 16 + 8) * OSTR + col] =
                make_float2(d[mt][nt][2], d[mt][nt][3]);
        }
    }
    if (PASS != 0) {
        #pragma unroll
        for (int nt = 0; nt < 8; nt++) {
            float c0 = d[0][nt][0] + d[0][nt][2] + d[1][nt][0] + d[1][nt][2];
            float c1 = d[0][nt][1] + d[0][nt][3] + d[1][nt][1] + d[1][nt][3];
            float q0 = d[0][nt][0] * d[0][nt][0] + d[0][nt][2] * d[0][nt][2] +
                       d[1][nt][0] * d[1][nt][0] + d[1][nt][2] * d[1][nt][2];
            float q1 = d[0][nt][1] * d[0][nt][1] + d[0][nt][3] * d[0][nt][3] +
                       d[1][nt][1] * d[1][nt][1] + d[1][nt][3] * d[1][nt][3];
            #pragma unroll
            for (int o = 4; o <= 16; o <<= 1) {
                c0 += __shfl_xor_sync(0xffffffffu, c0, o);
                c1 += __shfl_xor_sync(0xffffffffu, c1, o);
                q0 += __shfl_xor_sync(0xffffffffu, q0, o);
                q1 += __shfl_xor_sync(0xffffffffu, q1, o);
            }
            if (l < 4) {
                sbS[wr][wc * 64 + nt * 8 + l * 2]     = c0;
                sbS[wr][wc * 64 + nt * 8 + l * 2 + 1] = c1;
                sbQ[wr][wc * 64 + nt * 8 + l * 2]     = q0;
                sbQ[wr][wc * 64 + nt * 8 + l * 2 + 1] = q1;
            }
        }
        __syncthreads();
        if (t < 128) {
            float S = sbS[0][t] + sbS[1][t] + sbS[2][t] + sbS[3][t];
            float Q = sbQ[0][t] + sbQ[1][t] + sbQ[2][t] + sbQ[3][t];
            atomicAdd(&g_red[SOUT + nb * 128 + t], S);
            atomicAdd(&g_red[SOUT + 256 + nb * 128 + t], Q);
        }
    }
}

// ---------------- s_i / s_j from g_xlin ----------------
__global__ __launch_bounds__(256) void k_sij(const float* __restrict__ ai,
                                             const float* __restrict__ aj) {
    __shared__ float sai[128], saj[128];
    int t = threadIdx.x;
    if (t < 128) { sai[t] = ai[t]; saj[t] = aj[t]; }
    __syncthreads();
    int w = t >> 5, l = t & 31;
    int m = blockIdx.x * 8 + w;
    float4 x4 = *(const float4*)&g_xlin[m * 128 + l * 4];
    float pi = x4.x * sai[l * 4] + x4.y * sai[l * 4 + 1] +
               x4.z * sai[l * 4 + 2] + x4.w * sai[l * 4 + 3];
    float pj = x4.x * saj[l * 4] + x4.y * saj[l * 4 + 1] +
               x4.z * saj[l * 4 + 2] + x4.w * saj[l * 4 + 3];
    for (int o = 16; o > 0; o >>= 1) {
        pi += __shfl_xor_sync(0xffffffffu, pi, o);
        pj += __shfl_xor_sync(0xffffffffu, pj, o);
    }
    if (l == 0) {
        int n = m & (N_ - 1);
        g_si[m] = pi + g_ei[n];
        g_sj[m] = pj + g_ej[n];
    }
}

// ---------------- attention aggregation + agg stats ----------------
__global__ __launch_bounds__(128) void k_attn() {
    __shared__ float alpha[33];
    __shared__ int   ssrc[33];
    int t = threadIdx.x;
    int m0 = blockIdx.x * 4;
    float ssum = 0.0f, ssq = 0.0f;
    for (int rr = 0; rr < 4; rr++) {
        int m = m0 + rr;
        int b = m >> 9;
        int i = m & (N_ - 1);
        if (t < 32) {
            int src = g_topk[i * K_ + t];
            ssrc[t] = src;
            float sim = g_si[m];
            float v  = sim + g_sj[b * N_ + src];
            float lg = v > 0.0f ? v : 0.2f * v;
            bool valid = (src != i);
            if (!valid) lg = -1e30f;
            float vs  = sim + g_sj[m];
            float lgs = vs > 0.0f ? vs : 0.2f * vs;
            float mx = lg;
            for (int o = 16; o > 0; o >>= 1)
                mx = fmaxf(mx, __shfl_xor_sync(0xffffffffu, mx, o));
            mx = fmaxf(mx, lgs);
            float e  = valid ? expf(lg - mx) : 0.0f;
            float es = expf(lgs - mx);
            float den = e;
            for (int o = 16; o > 0; o >>= 1)
                den += __shfl_xor_sync(0xffffffffu, den, o);
            den += es;
            alpha[t] = e / den;
            if (t == 0) { alpha[32] = es / den; ssrc[32] = i; }
        }
        __syncthreads();
        int bbase = b * N_;
        float acc = 0.0f;
        #pragma unroll
        for (int k = 0; k < 33; k++)
            acc += alpha[k] * g_xlin[(bbase + ssrc[k]) * D_ + t];
        g_agg[m * D_ + t] = acc;
        ssum += acc; ssq += acc * acc;
        __syncthreads();
    }
    atomicAdd(&g_red[t], ssum);
    atomicAdd(&g_red[D_ + t], ssq);
}

// ---------------- gcn = relu(bn(agg)); h = gcn*emb + h stats ----------------
__global__ __launch_bounds__(128) void k_h(const float* __restrict__ emb,
                                           const float* __restrict__ g0,
                                           const float* __restrict__ b0) {
    int d = threadIdx.x;
    int r0 = blockIdx.x * 64;
    const float invM = 1.0f / (float)M_;
    float mean = g_red[d] * invM;
    float var  = g_red[D_ + d] * invM - mean * mean;
    float sc = rsqrtf(var + EPS_) * g0[d];
    float sh = b0[d] - mean * sc;
    float ssum = 0.0f, ssq = 0.0f;
    for (int r = r0; r < r0 + 64; r++) {
        float a = g_agg[r * D_ + d];
        float gcn = fmaxf(a * sc + sh, 0.0f);
        float h = gcn * emb[(r & (N_ - 1)) * D_ + d];
        g_h[r * D_ + d] = h;
        ssum += h; ssq += h * h;
    }
    atomicAdd(&g_red[256 + d], ssum);
    atomicAdd(&g_red[384 + d], ssq);
}

// ---------------- final: out = relu(bn(o2)) @ W3 + b3 ----------------
__global__ __launch_bounds__(256) void k_out(const float* __restrict__ W3,
                                             const float* __restrict__ b3,
                                             const float* __restrict__ g2,
                                             const float* __restrict__ b2v,
                                             float* __restrict__ out) {
    __shared__ float nsc[256], nsh[256], w[256];
    int t = threadIdx.x;
    const float invM = 1.0f / (float)M_;
    {
        float mean = g_red[1024 + t] * invM;
        float var  = g_red[1280 + t] * invM - mean * mean;
        float s = rsqrtf(var + EPS_) * g2[t];
        nsc[t] = s; nsh[t] = b2v[t] - mean * s; w[t] = W3[t];
    }
    __syncthreads();
    int warp = t >> 5, lane = t & 31;
    int m = blockIdx.x * 8 + warp;
    float acc = 0.0f;
    #pragma unroll
    for (int f = lane; f < 256; f += 32) {
        float v = g_o2[m * 256 + f];
        acc += fmaxf(v * nsc[f] + nsh[f], 0.0f) * w[f];
    }
    for (int o = 16; o > 0; o >>= 1)
        acc += __shfl_xor_sync(0xffffffffu, acc, o);
    if (lane == 0) out[m] = acc + b3[0];
}

// ---------------- launch ----------------
extern "C" void kernel_launch(void* const* d_in, const int* in_sizes, int n_in,
                              void* d_out, int out_size) {
    const float* data   = (const float*)d_in[0];
    const float* emb    = (const float*)d_in[1];
    const float* lin_W  = (const float*)d_in[2];
    const float* att_i  = (const float*)d_in[3];
    const float* att_j  = (const float*)d_in[4];
    const float* aem_i  = (const float*)d_in[5];
    const float* aem_j  = (const float*)d_in[6];
    // d_in[7] = gnn_bias : cancels exactly under BN
    const float* gnn_g  = (const float*)d_in[8];
    const float* gnn_b  = (const float*)d_in[9];
    const float* bno_g  = (const float*)d_in[10];
    const float* bno_b  = (const float*)d_in[11];
    const float* W1     = (const float*)d_in[12];
    // d_in[13] = b1 : cancels
    const float* bn1_g  = (const float*)d_in[14];
    const float* bn1_b  = (const float*)d_in[15];
    const float* W2     = (const float*)d_in[16];
    // d_in[17] = b2 : cancels
    const float* bn2_g  = (const float*)d_in[18];
    const float* bn2_b  = (const float*)d_in[19];
    const float* W3     = (const float*)d_in[20];
    const float* b3     = (const float*)d_in[21];
    float* out = (float*)d_out;

    k_zero<<<6, 256>>>();
    k_prepW<<<112, 1024>>>(lin_W, W1, W2);
    k_pre<<<N_, 128>>>(emb, aem_i, aem_j);
    k_topk<<<N_, 128>>>(emb);
    k_gemm<0><<<dim3(M_ / 128, 1), 256>>>(data, nullptr, nullptr);
    k_sij<<<M_ / 8, 256>>>(att_i, att_j);
    k_attn<<<M_ / 4, 128>>>();
    k_h<<<M_ / 64, 128>>>(emb, gnn_g, gnn_b);
    k_gemm<1><<<dim3(M_ / 128, 2), 256>>>(nullptr, bno_g, bno_b);
    k_gemm<2><<<dim3(M_ / 128, 2), 256>>>(nullptr, bn1_g, bn1_b);
    k_out<<<M_ / 8, 256>>>(W3, b3, bn2_g, bn2_b, out);
}

// round 6
// speedup vs baseline: 2.4578x; 1.5791x over previous
#include <cuda_runtime.h>
#include <cuda_bf16.h>
#include <math.h>
#include <stdint.h>

#define B_ 64
#define N_ 512
#define D_ 128
#define K_ 32
#define M_ (B_ * N_)
#define EPS_ 1e-5f

typedef unsigned long long ull;
typedef unsigned short ushort_t;

// ---------------- device scratch ----------------
__device__ float g_xlin[M_ * D_];
__device__ float g_si[M_];
__device__ float g_sj[M_];
__device__ float g_ei[N_];
__device__ float g_ej[N_];
__device__ float g_nrm[N_];
__device__ float g_cos[N_ * N_];
__device__ int   g_topk[N_ * K_];
__device__ float g_agg[M_ * D_];
__device__ float g_h[M_ * D_];
__device__ float g_o1[M_ * 256];
__device__ float g_o2[M_ * 256];
// W images: [n][k] row-major bf16, hi/lo split
__device__ __nv_bfloat16 g_Wh0[128 * 128], g_Wl0[128 * 128];
__device__ __nv_bfloat16 g_Wh1[256 * 128], g_Wl1[256 * 128];
__device__ __nv_bfloat16 g_Wh2[256 * 256], g_Wl2[256 * 256];
// stats: [0]=agg sum(128) [128]=agg sq [256]=h sum [384]=h sq
//        [512]=o1 sum(256) [768]=o1 sq [1024]=o2 sum [1280]=o2 sq
__device__ float g_red[1536];

// ---------------- helpers ----------------
__device__ __forceinline__ uint32_t smem_to_u32(const void* p) {
    uint32_t a;
    asm("{ .reg .u64 t; cvta.to.shared.u64 t, %1; cvt.u32.u64 %0, t; }"
        : "=r"(a) : "l"(p));
    return a;
}
__device__ __forceinline__ ushort_t bf_hi(float f, ushort_t& lo) {
    __nv_bfloat16 h = __float2bfloat16(f);
    float r = f - __bfloat162float(h);
    lo = __bfloat16_as_ushort(__float2bfloat16(r));
    return __bfloat16_as_ushort(h);
}
__device__ __forceinline__ ull pack4(ushort_t a, ushort_t b, ushort_t c, ushort_t d) {
    return (ull)a | ((ull)b << 16) | ((ull)c << 32) | ((ull)d << 48);
}
#define LDSM_X4(r0, r1, r2, r3, addr) \
    asm volatile("ldmatrix.sync.aligned.m8n8.x4.shared.b16 {%0,%1,%2,%3}, [%4];" \
                 : "=r"(r0), "=r"(r1), "=r"(r2), "=r"(r3) : "r"(addr))
#define MMA(dd, aa, b0v, b1v) \
    asm volatile("mma.sync.aligned.m16n8k16.row.col.f32.bf16.bf16.f32 " \
                 "{%0,%1,%2,%3}, {%4,%5,%6,%7}, {%8,%9}, {%0,%1,%2,%3};" \
                 : "+f"((dd)[0]), "+f"((dd)[1]), "+f"((dd)[2]), "+f"((dd)[3]) \
                 : "r"((aa)[0]), "r"((aa)[1]), "r"((aa)[2]), "r"((aa)[3]), \
                   "r"(b0v), "r"(b1v))

// ---------------- zero stats ----------------
__global__ void k_zero() {
    int i = blockIdx.x * 256 + threadIdx.x;
    if (i < 1536) g_red[i] = 0.0f;
}

// ---------------- W prep: transpose + bf16 split into [n][k] images ---------
__global__ __launch_bounds__(1024) void k_prepW(const float* __restrict__ linW,
                                                const float* __restrict__ W1,
                                                const float* __restrict__ W2) {
    int id = blockIdx.x * 1024 + threadIdx.x;  // 112*1024 = 114688
    if (id < 16384) {
        int n = id >> 7, k = id & 127;
        ushort_t lo; ushort_t hi = bf_hi(linW[k * 128 + n], lo);
        g_Wh0[n * 128 + k] = __ushort_as_bfloat16(hi);
        g_Wl0[n * 128 + k] = __ushort_as_bfloat16(lo);
    } else if (id < 49152) {
        int e = id - 16384;
        int n = e >> 7, k = e & 127;
        ushort_t lo; ushort_t hi = bf_hi(W1[k * 256 + n], lo);
        g_Wh1[n * 128 + k] = __ushort_as_bfloat16(hi);
        g_Wl1[n * 128 + k] = __ushort_as_bfloat16(lo);
    } else {
        int e = id - 49152;
        int n = e >> 8, k = e & 255;
        ushort_t lo; ushort_t hi = bf_hi(W2[k * 256 + n], lo);
        g_Wh2[n * 256 + k] = __ushort_as_bfloat16(hi);
        g_Wl2[n * 256 + k] = __ushort_as_bfloat16(lo);
    }
}

// ---------------- per-node: norm + emb attention parts ----------------
__global__ void k_pre(const float* __restrict__ emb,
                      const float* __restrict__ aei,
                      const float* __restrict__ aej) {
    int n = blockIdx.x;
    int t = threadIdx.x;  // 128
    float v = emb[n * D_ + t];
    float s2 = v * v, pi = v * aei[t], pj = v * aej[t];
    for (int o = 16; o > 0; o >>= 1) {
        s2 += __shfl_xor_sync(0xffffffffu, s2, o);
        pi += __shfl_xor_sync(0xffffffffu, pi, o);
        pj += __shfl_xor_sync(0xffffffffu, pj, o);
    }
    __shared__ float sh[3][4];
    int w = t >> 5, l = t & 31;
    if (l == 0) { sh[0][w] = s2; sh[1][w] = pi; sh[2][w] = pj; }
    __syncthreads();
    if (t == 0) {
        float a = 0, b = 0, c = 0;
        for (int q = 0; q < 4; q++) { a += sh[0][q]; b += sh[1][q]; c += sh[2][q]; }
        g_nrm[n] = sqrtf(a);
        g_ei[n] = b;
        g_ej[n] = c;
    }
}

// ---------------- cosine Gram matrix: g_cos = normalized emb @ emb^T --------
// 64x64 tile per block, grid (8,8). Both tiles k-major in smem -> LDS
// conflict-free (all reads within a 256B row).
__global__ __launch_bounds__(256) void k_gram(const float* __restrict__ emb) {
    __shared__ float Ash[128][64];
    __shared__ float Bsh[128][64];
    int t = threadIdx.x;
    int i0 = blockIdx.x * 64, j0 = blockIdx.y * 64;
    int r = t & 63, kq0 = t >> 6;
    #pragma unroll
    for (int q = 0; q < 8; q++) {
        int kq = kq0 + q * 4;
        float4 a = *(const float4*)&emb[(i0 + r) * 128 + kq * 4];
        Ash[kq * 4 + 0][r] = a.x; Ash[kq * 4 + 1][r] = a.y;
        Ash[kq * 4 + 2][r] = a.z; Ash[kq * 4 + 3][r] = a.w;
        float4 b = *(const float4*)&emb[(j0 + r) * 128 + kq * 4];
        Bsh[kq * 4 + 0][r] = b.x; Bsh[kq * 4 + 1][r] = b.y;
        Bsh[kq * 4 + 2][r] = b.z; Bsh[kq * 4 + 3][r] = b.w;
    }
    __syncthreads();
    int tr = t >> 4, tc = t & 15;
    float acc[4][4] = {};
    #pragma unroll 4
    for (int k = 0; k < 128; k++) {
        float4 av = *(float4*)&Ash[k][tr * 4];
        float4 bv = *(float4*)&Bsh[k][tc * 4];
        acc[0][0] += av.x * bv.x; acc[0][1] += av.x * bv.y;
        acc[0][2] += av.x * bv.z; acc[0][3] += av.x * bv.w;
        acc[1][0] += av.y * bv.x; acc[1][1] += av.y * bv.y;
        acc[1][2] += av.y * bv.z; acc[1][3] += av.y * bv.w;
        acc[2][0] += av.z * bv.x; acc[2][1] += av.z * bv.y;
        acc[2][2] += av.z * bv.z; acc[2][3] += av.z * bv.w;
        acc[3][0] += av.w * bv.x; acc[3][1] += av.w * bv.y;
        acc[3][2] += av.w * bv.z; acc[3][3] += av.w * bv.w;
    }
    float invi[4], invj[4];
    #pragma unroll
    for (int q = 0; q < 4; q++) {
        invi[q] = 1.0f / g_nrm[i0 + tr * 4 + q];
        invj[q] = 1.0f / g_nrm[j0 + tc * 4 + q];
    }
    #pragma unroll
    for (int rr = 0; rr < 4; rr++) {
        float s = invi[rr];
        *(float4*)&g_cos[(i0 + tr * 4 + rr) * N_ + j0 + tc * 4] =
            make_float4(acc[rr][0] * s * invj[0], acc[rr][1] * s * invj[1],
                        acc[rr][2] * s * invj[2], acc[rr][3] * s * invj[3]);
    }
}

// ---------------- topk selection: one warp per row, no block barriers -------
__global__ __launch_bounds__(256) void k_sel() {
    __shared__ float sv[8][512];
    int t = threadIdx.x, w = t >> 5, lane = t & 31;
    int i = blockIdx.x * 8 + w;
    float* v = sv[w];
    #pragma unroll
    for (int q = 0; q < 16; q++)
        v[q * 32 + lane] = g_cos[i * N_ + q * 32 + lane];
    // local max (first occurrence = min local index)
    float lv = v[lane]; int li = 0;
    #pragma unroll
    for (int q = 1; q < 16; q++) {
        float x = v[q * 32 + lane];
        if (x > lv) { lv = x; li = q; }
    }
    for (int k = 0; k < K_; k++) {
        float bv = lv;
        int bj = li * 32 + lane;
        #pragma unroll
        for (int o = 16; o > 0; o >>= 1) {
            float ov = __shfl_xor_sync(0xffffffffu, bv, o);
            int oj = __shfl_xor_sync(0xffffffffu, bj, o);
            if (ov > bv || (ov == bv && oj < bj)) { bv = ov; bj = oj; }
        }
        if (lane == 0) g_topk[i * K_ + k] = bj;
        if ((bj & 31) == lane) {
            v[bj] = -2.0f;
            lv = v[lane]; li = 0;
            #pragma unroll
            for (int q = 1; q < 16; q++) {
                float x = v[q * 32 + lane];
                if (x > lv) { lv = x; li = q; }
            }
        }
        __syncwarp();
    }
}

// ---------------- unified HMMA GEMM (3-term bf16 split) ----------------
template <int PASS>
__global__ __launch_bounds__(256) void k_gemm(const float* __restrict__ Xext,
                                              const float* __restrict__ gin,
                                              const float* __restrict__ bin) {
    constexpr int KD   = (PASS == 2) ? 256 : 128;
    constexpr int OSTR = (PASS == 0) ? 128 : 256;
    constexpr int SIN  = (PASS == 1) ? 256 : 512;
    constexpr int SOUT = (PASS == 1) ? 512 : 1024;

    __shared__ __align__(16) __nv_bfloat16 Xh[128 * 40];
    __shared__ __align__(16) __nv_bfloat16 Xl[128 * 40];
    __shared__ __align__(16) __nv_bfloat16 Wh[128 * 40];
    __shared__ __align__(16) __nv_bfloat16 Wl[128 * 40];
    __shared__ float nsc[256], nsh[256];
    __shared__ float sbS[4][128], sbQ[4][128];

    const float* __restrict__ Xg =
        (PASS == 0) ? Xext : ((PASS == 1) ? g_h : g_o1);
    float* __restrict__ outg =
        (PASS == 0) ? g_xlin : ((PASS == 1) ? g_o1 : g_o2);
    const __nv_bfloat16* Wgh = (PASS == 0) ? g_Wh0 : ((PASS == 1) ? g_Wh1 : g_Wh2);
    const __nv_bfloat16* Wgl = (PASS == 0) ? g_Wl0 : ((PASS == 1) ? g_Wl1 : g_Wl2);

    int t = threadIdx.x, l = t & 31, w = t >> 5;
    int wr = w >> 1, wc = w & 1;
    int row0 = blockIdx.x * 128;
    int nb = blockIdx.y;
    const __nv_bfloat16* WghB = Wgh + nb * 128 * KD;
    const __nv_bfloat16* WglB = Wgl + nb * 128 * KD;

    if (PASS != 0) {
        const float invM = 1.0f / (float)M_;
        if (t < KD) {
            float mean = g_red[SIN + t] * invM;
            float var  = g_red[SIN + KD + t] * invM - mean * mean;
            float s = rsqrtf(var + EPS_) * gin[t];
            nsc[t] = s; nsh[t] = bin[t] - mean * s;
        }
        __syncthreads();
    }

    float d[2][8][4] = {};
    uint32_t xh_b = smem_to_u32(Xh), xl_b = smem_to_u32(Xl);
    uint32_t wh_b = smem_to_u32(Wh), wl_b = smem_to_u32(Wl);

    for (int kb = 0; kb < KD; kb += 32) {
        #pragma unroll
        for (int v = t; v < 1024; v += 256) {
            int r = v >> 3, k4 = (v & 7) * 4;
            float4 x4 = *(const float4*)&Xg[(row0 + r) * KD + kb + k4];
            float f0, f1, f2, f3;
            if (PASS == 0) {
                f0 = x4.x; f1 = x4.y; f2 = x4.z; f3 = x4.w;
            } else {
                int fc = kb + k4;
                f0 = fmaxf(x4.x * nsc[fc + 0] + nsh[fc + 0], 0.0f);
                f1 = fmaxf(x4.y * nsc[fc + 1] + nsh[fc + 1], 0.0f);
                f2 = fmaxf(x4.z * nsc[fc + 2] + nsh[fc + 2], 0.0f);
                f3 = fmaxf(x4.w * nsc[fc + 3] + nsh[fc + 3], 0.0f);
            }
            ushort_t l0, l1, l2, l3;
            ushort_t h0 = bf_hi(f0, l0), h1 = bf_hi(f1, l1);
            ushort_t h2 = bf_hi(f2, l2), h3 = bf_hi(f3, l3);
            *(ull*)(&Xh[r * 40 + k4]) = pack4(h0, h1, h2, h3);
            *(ull*)(&Xl[r * 40 + k4]) = pack4(l0, l1, l2, l3);
        }
        #pragma unroll
        for (int v = t; v < 512; v += 256) {
            int n = v >> 2, k8 = (v & 3) * 8;
            *(float4*)&Wh[n * 40 + k8] = *(const float4*)&WghB[n * KD + kb + k8];
            *(float4*)&Wl[n * 40 + k8] = *(const float4*)&WglB[n * KD + kb + k8];
        }
        __syncthreads();
        #pragma unroll
        for (int ks = 0; ks < 32; ks += 16) {
            uint32_t ah[2][4], al[2][4];
            uint32_t arow = (uint32_t)(l & 15);
            uint32_t akoff = (uint32_t)((l >> 4) << 3);
            #pragma unroll
            for (int mt = 0; mt < 2; mt++) {
                uint32_t off = ((wr * 32 + mt * 16 + arow) * 40 + ks + akoff) * 2;
                LDSM_X4(ah[mt][0], ah[mt][1], ah[mt][2], ah[mt][3], xh_b + off);
                LDSM_X4(al[mt][0], al[mt][1], al[mt][2], al[mt][3], xl_b + off);
            }
            uint32_t brow = (uint32_t)(((l >> 4) << 3) + (l & 7));
            uint32_t bkoff = (uint32_t)(((l >> 3) & 1) << 3);
            #pragma unroll
            for (int g = 0; g < 4; g++) {
                uint32_t off = ((wc * 64 + g * 16 + brow) * 40 + ks + bkoff) * 2;
                uint32_t bh[4], bl[4];
                LDSM_X4(bh[0], bh[1], bh[2], bh[3], wh_b + off);
                LDSM_X4(bl[0], bl[1], bl[2], bl[3], wl_b + off);
                #pragma unroll
                for (int mt = 0; mt < 2; mt++) {
                    MMA(d[mt][2 * g],     ah[mt], bh[0], bh[1]);
                    MMA(d[mt][2 * g],     ah[mt], bl[0], bl[1]);
                    MMA(d[mt][2 * g],     al[mt], bh[0], bh[1]);
                    MMA(d[mt][2 * g + 1], ah[mt], bh[2], bh[3]);
                    MMA(d[mt][2 * g + 1], ah[mt], bl[2], bl[3]);
                    MMA(d[mt][2 * g + 1], al[mt], bh[2], bh[3]);
                }
            }
        }
        __syncthreads();
    }

    int rbase = row0 + wr * 32 + (l >> 2);
    int cbase = nb * 128 + wc * 64 + (l & 3) * 2;
    #pragma unroll
    for (int mt = 0; mt < 2; mt++) {
        #pragma unroll
        for (int nt = 0; nt < 8; nt++) {
            int col = cbase + nt * 8;
            *(float2*)&outg[(rbase + mt * 16) * OSTR + col] =
                make_float2(d[mt][nt][0], d[mt][nt][1]);
            *(float2*)&outg[(rbase + mt * 16 + 8) * OSTR + col] =
                make_float2(d[mt][nt][2], d[mt][nt][3]);
        }
    }
    if (PASS != 0) {
        #pragma unroll
        for (int nt = 0; nt < 8; nt++) {
            float c0 = d[0][nt][0] + d[0][nt][2] + d[1][nt][0] + d[1][nt][2];
            float c1 = d[0][nt][1] + d[0][nt][3] + d[1][nt][1] + d[1][nt][3];
            float q0 = d[0][nt][0] * d[0][nt][0] + d[0][nt][2] * d[0][nt][2] +
                       d[1][nt][0] * d[1][nt][0] + d[1][nt][2] * d[1][nt][2];
            float q1 = d[0][nt][1] * d[0][nt][1] + d[0][nt][3] * d[0][nt][3] +
                       d[1][nt][1] * d[1][nt][1] + d[1][nt][3] * d[1][nt][3];
            #pragma unroll
            for (int o = 4; o <= 16; o <<= 1) {
                c0 += __shfl_xor_sync(0xffffffffu, c0, o);
                c1 += __shfl_xor_sync(0xffffffffu, c1, o);
                q0 += __shfl_xor_sync(0xffffffffu, q0, o);
                q1 += __shfl_xor_sync(0xffffffffu, q1, o);
            }
            if (l < 4) {
                sbS[wr][wc * 64 + nt * 8 + l * 2]     = c0;
                sbS[wr][wc * 64 + nt * 8 + l * 2 + 1] = c1;
                sbQ[wr][wc * 64 + nt * 8 + l * 2]     = q0;
                sbQ[wr][wc * 64 + nt * 8 + l * 2 + 1] = q1;
            }
        }
        __syncthreads();
        if (t < 128) {
            float S = sbS[0][t] + sbS[1][t] + sbS[2][t] + sbS[3][t];
            float Q = sbQ[0][t] + sbQ[1][t] + sbQ[2][t] + sbQ[3][t];
            atomicAdd(&g_red[SOUT + nb * 128 + t], S);
            atomicAdd(&g_red[SOUT + 256 + nb * 128 + t], Q);
        }
    }
}

// ---------------- s_i / s_j from g_xlin ----------------
__global__ __launch_bounds__(256) void k_sij(const float* __restrict__ ai,
                                             const float* __restrict__ aj) {
    __shared__ float sai[128], saj[128];
    int t = threadIdx.x;
    if (t < 128) { sai[t] = ai[t]; saj[t] = aj[t]; }
    __syncthreads();
    int w = t >> 5, l = t & 31;
    int m = blockIdx.x * 8 + w;
    float4 x4 = *(const float4*)&g_xlin[m * 128 + l * 4];
    float pi = x4.x * sai[l * 4] + x4.y * sai[l * 4 + 1] +
               x4.z * sai[l * 4 + 2] + x4.w * sai[l * 4 + 3];
    float pj = x4.x * saj[l * 4] + x4.y * saj[l * 4 + 1] +
               x4.z * saj[l * 4 + 2] + x4.w * saj[l * 4 + 3];
    for (int o = 16; o > 0; o >>= 1) {
        pi += __shfl_xor_sync(0xffffffffu, pi, o);
        pj += __shfl_xor_sync(0xffffffffu, pj, o);
    }
    if (l == 0) {
        int n = m & (N_ - 1);
        g_si[m] = pi + g_ei[n];
        g_sj[m] = pj + g_ej[n];
    }
}

// ---------------- attention aggregation + agg stats ----------------
__global__ __launch_bounds__(128) void k_attn() {
    __shared__ float alpha[33];
    __shared__ int   ssrc[33];
    int t = threadIdx.x;
    int m0 = blockIdx.x * 4;
    float ssum = 0.0f, ssq = 0.0f;
    for (int rr = 0; rr < 4; rr++) {
        int m = m0 + rr;
        int b = m >> 9;
        int i = m & (N_ - 1);
        if (t < 32) {
            int src = g_topk[i * K_ + t];
            ssrc[t] = src;
            float sim = g_si[m];
            float v  = sim + g_sj[b * N_ + src];
            float lg = v > 0.0f ? v : 0.2f * v;
            bool valid = (src != i);
            if (!valid) lg = -1e30f;
            float vs  = sim + g_sj[m];
            float lgs = vs > 0.0f ? vs : 0.2f * vs;
            float mx = lg;
            for (int o = 16; o > 0; o >>= 1)
                mx = fmaxf(mx, __shfl_xor_sync(0xffffffffu, mx, o));
            mx = fmaxf(mx, lgs);
            float e  = valid ? expf(lg - mx) : 0.0f;
            float es = expf(lgs - mx);
            float den = e;
            for (int o = 16; o > 0; o >>= 1)
                den += __shfl_xor_sync(0xffffffffu, den, o);
            den += es;
            alpha[t] = e / den;
            if (t == 0) { alpha[32] = es / den; ssrc[32] = i; }
        }
        __syncthreads();
        int bbase = b * N_;
        float acc = 0.0f;
        #pragma unroll
        for (int k = 0; k < 33; k++)
            acc += alpha[k] * g_xlin[(bbase + ssrc[k]) * D_ + t];
        g_agg[m * D_ + t] = acc;
        ssum += acc; ssq += acc * acc;
        __syncthreads();
    }
    atomicAdd(&g_red[t], ssum);
    atomicAdd(&g_red[D_ + t], ssq);
}

// ---------------- gcn = relu(bn(agg)); h = gcn*emb + h stats ----------------
__global__ __launch_bounds__(128) void k_h(const float* __restrict__ emb,
                                           const float* __restrict__ g0,
                                           const float* __restrict__ b0) {
    int d = threadIdx.x;
    int r0 = blockIdx.x * 64;
    const float invM = 1.0f / (float)M_;
    float mean = g_red[d] * invM;
    float var  = g_red[D_ + d] * invM - mean * mean;
    float sc = rsqrtf(var + EPS_) * g0[d];
    float sh = b0[d] - mean * sc;
    float ssum = 0.0f, ssq = 0.0f;
    for (int r = r0; r < r0 + 64; r++) {
        float a = g_agg[r * D_ + d];
        float gcn = fmaxf(a * sc + sh, 0.0f);
        float h = gcn * emb[(r & (N_ - 1)) * D_ + d];
        g_h[r * D_ + d] = h;
        ssum += h; ssq += h * h;
    }
    atomicAdd(&g_red[256 + d], ssum);
    atomicAdd(&g_red[384 + d], ssq);
}

// ---------------- final: out = relu(bn(o2)) @ W3 + b3 ----------------
__global__ __launch_bounds__(256) void k_out(const float* __restrict__ W3,
                                             const float* __restrict__ b3,
                                             const float* __restrict__ g2,
                                             const float* __restrict__ b2v,
                                             float* __restrict__ out) {
    __shared__ float nsc[256], nsh[256], w[256];
    int t = threadIdx.x;
    const float invM = 1.0f / (float)M_;
    {
        float mean = g_red[1024 + t] * invM;
        float var  = g_red[1280 + t] * invM - mean * mean;
        float s = rsqrtf(var + EPS_) * g2[t];
        nsc[t] = s; nsh[t] = b2v[t] - mean * s; w[t] = W3[t];
    }
    __syncthreads();
    int warp = t >> 5, lane = t & 31;
    int m = blockIdx.x * 8 + warp;
    float acc = 0.0f;
    #pragma unroll
    for (int f = lane; f < 256; f += 32) {
        float v = g_o2[m * 256 + f];
        acc += fmaxf(v * nsc[f] + nsh[f], 0.0f) * w[f];
    }
    for (int o = 16; o > 0; o >>= 1)
        acc += __shfl_xor_sync(0xffffffffu, acc, o);
    if (lane == 0) out[m] = acc + b3[0];
}

// ---------------- launch ----------------
extern "C" void kernel_launch(void* const* d_in, const int* in_sizes, int n_in,
                              void* d_out, int out_size) {
    const float* data   = (const float*)d_in[0];
    const float* emb    = (const float*)d_in[1];
    const float* lin_W  = (const float*)d_in[2];
    const float* att_i  = (const float*)d_in[3];
    const float* att_j  = (const float*)d_in[4];
    const float* aem_i  = (const float*)d_in[5];
    const float* aem_j  = (const float*)d_in[6];
    // d_in[7] = gnn_bias : cancels exactly under BN
    const float* gnn_g  = (const float*)d_in[8];
    const float* gnn_b  = (const float*)d_in[9];
    const float* bno_g  = (const float*)d_in[10];
    const float* bno_b  = (const float*)d_in[11];
    const float* W1     = (const float*)d_in[12];
    // d_in[13] = b1 : cancels
    const float* bn1_g  = (const float*)d_in[14];
    const float* bn1_b  = (const float*)d_in[15];
    const float* W2     = (const float*)d_in[16];
    // d_in[17] = b2 : cancels
    const float* bn2_g  = (const float*)d_in[18];
    const float* bn2_b  = (const float*)d_in[19];
    const float* W3     = (const float*)d_in[20];
    const float* b3     = (const float*)d_in[21];
    float* out = (float*)d_out;

    k_zero<<<6, 256>>>();
    k_prepW<<<112, 1024>>>(lin_W, W1, W2);
    k_pre<<<N_, 128>>>(emb, aem_i, aem_j);
    k_gram<<<dim3(8, 8), 256>>>(emb);
    k_sel<<<64, 256>>>();
    k_gemm<0><<<dim3(M_ / 128, 1), 256>>>(data, nullptr, nullptr);
    k_sij<<<M_ / 8, 256>>>(att_i, att_j);
    k_attn<<<M_ / 4, 128>>>();
    k_h<<<M_ / 64, 128>>>(emb, gnn_g, gnn_b);
    k_gemm<1><<<dim3(M_ / 128, 2), 256>>>(nullptr, bno_g, bno_b);
    k_gemm<2><<<dim3(M_ / 128, 2), 256>>>(nullptr, bn1_g, bn1_b);
    k_out<<<M_ / 8, 256>>>(W3, b3, bn2_g, bn2_b, out);
}

// round 7
// speedup vs baseline: 2.5973x; 1.0568x over previous
#include <cuda_runtime.h>
#include <cuda_bf16.h>
#include <math.h>
#include <stdint.h>

#define B_ 64
#define N_ 512
#define D_ 128
#define K_ 32
#define M_ (B_ * N_)
#define EPS_ 1e-5f

typedef unsigned long long ull;
typedef unsigned short ushort_t;

// ---------------- device scratch ----------------
__device__ float g_xlin[M_ * D_];
__device__ float g_si[M_];
__device__ float g_sj[M_];
__device__ float g_ei[N_];
__device__ float g_ej[N_];
__device__ float g_nrm[N_];
__device__ float g_cos[N_ * N_];
__device__ int   g_topk[N_ * K_];
__device__ float g_agg[M_ * D_];
__device__ float g_h[M_ * D_];
__device__ float g_o1[M_ * 256];
__device__ float g_o2[M_ * 256];
// W images: [n][k] row-major bf16, hi/lo split
__device__ __nv_bfloat16 g_Wh0[128 * 128], g_Wl0[128 * 128];
__device__ __nv_bfloat16 g_Wh1[256 * 128], g_Wl1[256 * 128];
__device__ __nv_bfloat16 g_Wh2[256 * 256], g_Wl2[256 * 256];
// stats: [0]=agg sum(128) [128]=agg sq [256]=h sum [384]=h sq
//        [512]=o1 sum(256) [768]=o1 sq [1024]=o2 sum [1280]=o2 sq
__device__ float g_red[1536];

// ---------------- helpers ----------------
__device__ __forceinline__ uint32_t smem_to_u32(const void* p) {
    uint32_t a;
    asm("{ .reg .u64 t; cvta.to.shared.u64 t, %1; cvt.u32.u64 %0, t; }"
        : "=r"(a) : "l"(p));
    return a;
}
__device__ __forceinline__ ushort_t bf_hi(float f, ushort_t& lo) {
    __nv_bfloat16 h = __float2bfloat16(f);
    float r = f - __bfloat162float(h);
    lo = __bfloat16_as_ushort(__float2bfloat16(r));
    return __bfloat16_as_ushort(h);
}
__device__ __forceinline__ ull pack4(ushort_t a, ushort_t b, ushort_t c, ushort_t d) {
    return (ull)a | ((ull)b << 16) | ((ull)c << 32) | ((ull)d << 48);
}
#define LDSM_X4(r0, r1, r2, r3, addr) \
    asm volatile("ldmatrix.sync.aligned.m8n8.x4.shared.b16 {%0,%1,%2,%3}, [%4];" \
                 : "=r"(r0), "=r"(r1), "=r"(r2), "=r"(r3) : "r"(addr))
#define MMA(dd, aa, b0v, b1v) \
    asm volatile("mma.sync.aligned.m16n8k16.row.col.f32.bf16.bf16.f32 " \
                 "{%0,%1,%2,%3}, {%4,%5,%6,%7}, {%8,%9}, {%0,%1,%2,%3};" \
                 : "+f"((dd)[0]), "+f"((dd)[1]), "+f"((dd)[2]), "+f"((dd)[3]) \
                 : "r"((aa)[0]), "r"((aa)[1]), "r"((aa)[2]), "r"((aa)[3]), \
                   "r"(b0v), "r"(b1v))

// ---------------- zero stats ----------------
__global__ void k_zero() {
    int i = blockIdx.x * 256 + threadIdx.x;
    if (i < 1536) g_red[i] = 0.0f;
}

// ---------------- W prep: transpose + bf16 split into [n][k] images ---------
__global__ __launch_bounds__(1024) void k_prepW(const float* __restrict__ linW,
                                                const float* __restrict__ W1,
                                                const float* __restrict__ W2) {
    int id = blockIdx.x * 1024 + threadIdx.x;  // 112*1024 = 114688
    if (id < 16384) {
        int n = id >> 7, k = id & 127;
        ushort_t lo; ushort_t hi = bf_hi(linW[k * 128 + n], lo);
        g_Wh0[n * 128 + k] = __ushort_as_bfloat16(hi);
        g_Wl0[n * 128 + k] = __ushort_as_bfloat16(lo);
    } else if (id < 49152) {
        int e = id - 16384;
        int n = e >> 7, k = e & 127;
        ushort_t lo; ushort_t hi = bf_hi(W1[k * 256 + n], lo);
        g_Wh1[n * 128 + k] = __ushort_as_bfloat16(hi);
        g_Wl1[n * 128 + k] = __ushort_as_bfloat16(lo);
    } else {
        int e = id - 49152;
        int n = e >> 8, k = e & 255;
        ushort_t lo; ushort_t hi = bf_hi(W2[k * 256 + n], lo);
        g_Wh2[n * 256 + k] = __ushort_as_bfloat16(hi);
        g_Wl2[n * 256 + k] = __ushort_as_bfloat16(lo);
    }
}

// ---------------- per-node: norm + emb attention parts ----------------
__global__ void k_pre(const float* __restrict__ emb,
                      const float* __restrict__ aei,
                      const float* __restrict__ aej) {
    int n = blockIdx.x;
    int t = threadIdx.x;  // 128
    float v = emb[n * D_ + t];
    float s2 = v * v, pi = v * aei[t], pj = v * aej[t];
    for (int o = 16; o > 0; o >>= 1) {
        s2 += __shfl_xor_sync(0xffffffffu, s2, o);
        pi += __shfl_xor_sync(0xffffffffu, pi, o);
        pj += __shfl_xor_sync(0xffffffffu, pj, o);
    }
    __shared__ float sh[3][4];
    int w = t >> 5, l = t & 31;
    if (l == 0) { sh[0][w] = s2; sh[1][w] = pi; sh[2][w] = pj; }
    __syncthreads();
    if (t == 0) {
        float a = 0, b = 0, c = 0;
        for (int q = 0; q < 4; q++) { a += sh[0][q]; b += sh[1][q]; c += sh[2][q]; }
        g_nrm[n] = sqrtf(a);
        g_ei[n] = b;
        g_ej[n] = c;
    }
}

// ---------------- cosine Gram matrix ----------------
__global__ __launch_bounds__(256) void k_gram(const float* __restrict__ emb) {
    __shared__ float Ash[128][64];
    __shared__ float Bsh[128][64];
    int t = threadIdx.x;
    int i0 = blockIdx.x * 64, j0 = blockIdx.y * 64;
    int r = t & 63, kq0 = t >> 6;
    #pragma unroll
    for (int q = 0; q < 8; q++) {
        int kq = kq0 + q * 4;
        float4 a = *(const float4*)&emb[(i0 + r) * 128 + kq * 4];
        Ash[kq * 4 + 0][r] = a.x; Ash[kq * 4 + 1][r] = a.y;
        Ash[kq * 4 + 2][r] = a.z; Ash[kq * 4 + 3][r] = a.w;
        float4 b = *(const float4*)&emb[(j0 + r) * 128 + kq * 4];
        Bsh[kq * 4 + 0][r] = b.x; Bsh[kq * 4 + 1][r] = b.y;
        Bsh[kq * 4 + 2][r] = b.z; Bsh[kq * 4 + 3][r] = b.w;
    }
    __syncthreads();
    int tr = t >> 4, tc = t & 15;
    float acc[4][4] = {};
    #pragma unroll 4
    for (int k = 0; k < 128; k++) {
        float4 av = *(float4*)&Ash[k][tr * 4];
        float4 bv = *(float4*)&Bsh[k][tc * 4];
        acc[0][0] += av.x * bv.x; acc[0][1] += av.x * bv.y;
        acc[0][2] += av.x * bv.z; acc[0][3] += av.x * bv.w;
        acc[1][0] += av.y * bv.x; acc[1][1] += av.y * bv.y;
        acc[1][2] += av.y * bv.z; acc[1][3] += av.y * bv.w;
        acc[2][0] += av.z * bv.x; acc[2][1] += av.z * bv.y;
        acc[2][2] += av.z * bv.z; acc[2][3] += av.z * bv.w;
        acc[3][0] += av.w * bv.x; acc[3][1] += av.w * bv.y;
        acc[3][2] += av.w * bv.z; acc[3][3] += av.w * bv.w;
    }
    float invi[4], invj[4];
    #pragma unroll
    for (int q = 0; q < 4; q++) {
        invi[q] = 1.0f / g_nrm[i0 + tr * 4 + q];
        invj[q] = 1.0f / g_nrm[j0 + tc * 4 + q];
    }
    #pragma unroll
    for (int rr = 0; rr < 4; rr++) {
        float s = invi[rr];
        *(float4*)&g_cos[(i0 + tr * 4 + rr) * N_ + j0 + tc * 4] =
            make_float4(acc[rr][0] * s * invj[0], acc[rr][1] * s * invj[1],
                        acc[rr][2] * s * invj[2], acc[rr][3] * s * invj[3]);
    }
}

// ---------------- topk selection: one warp per row ----------------
__global__ __launch_bounds__(256) void k_sel() {
    __shared__ float sv[8][512];
    int t = threadIdx.x, w = t >> 5, lane = t & 31;
    int i = blockIdx.x * 8 + w;
    float* v = sv[w];
    #pragma unroll
    for (int q = 0; q < 16; q++)
        v[q * 32 + lane] = g_cos[i * N_ + q * 32 + lane];
    float lv = v[lane]; int li = 0;
    #pragma unroll
    for (int q = 1; q < 16; q++) {
        float x = v[q * 32 + lane];
        if (x > lv) { lv = x; li = q; }
    }
    for (int k = 0; k < K_; k++) {
        float bv = lv;
        int bj = li * 32 + lane;
        #pragma unroll
        for (int o = 16; o > 0; o >>= 1) {
            float ov = __shfl_xor_sync(0xffffffffu, bv, o);
            int oj = __shfl_xor_sync(0xffffffffu, bj, o);
            if (ov > bv || (ov == bv && oj < bj)) { bv = ov; bj = oj; }
        }
        if (lane == 0) g_topk[i * K_ + k] = bj;
        if ((bj & 31) == lane) {
            v[bj] = -2.0f;
            lv = v[lane]; li = 0;
            #pragma unroll
            for (int q = 1; q < 16; q++) {
                float x = v[q * 32 + lane];
                if (x > lv) { lv = x; li = q; }
            }
        }
        __syncwarp();
    }
}

// ---------------- unified HMMA GEMM (3-term bf16 split) ----------------
// PASS 0: g_xlin = data @ linW ; epilogue computes g_si/g_sj (gin=att_i, bin=att_j)
// PASS 1: g_o1 = relu(bn(g_h)) @ W1   ; PASS 2: g_o2 = relu(bn(g_o1)) @ W2
template <int PASS>
__global__ __launch_bounds__(256) void k_gemm(const float* __restrict__ Xext,
                                              const float* __restrict__ gin,
                                              const float* __restrict__ bin) {
    constexpr int KD   = (PASS == 2) ? 256 : 128;
    constexpr int OSTR = (PASS == 0) ? 128 : 256;
    constexpr int SIN  = (PASS == 1) ? 256 : 512;
    constexpr int SOUT = (PASS == 1) ? 512 : 1024;

    __shared__ __align__(16) __nv_bfloat16 Xh[128 * 40];
    __shared__ __align__(16) __nv_bfloat16 Xl[128 * 40];
    __shared__ __align__(16) __nv_bfloat16 Wh[128 * 40];
    __shared__ __align__(16) __nv_bfloat16 Wl[128 * 40];
    __shared__ float nsc[256], nsh[256];
    __shared__ float sbS[4][128], sbQ[4][128];

    const float* __restrict__ Xg =
        (PASS == 0) ? Xext : ((PASS == 1) ? g_h : g_o1);
    float* __restrict__ outg =
        (PASS == 0) ? g_xlin : ((PASS == 1) ? g_o1 : g_o2);
    const __nv_bfloat16* Wgh = (PASS == 0) ? g_Wh0 : ((PASS == 1) ? g_Wh1 : g_Wh2);
    const __nv_bfloat16* Wgl = (PASS == 0) ? g_Wl0 : ((PASS == 1) ? g_Wl1 : g_Wl2);

    int t = threadIdx.x, l = t & 31, w = t >> 5;
    int wr = w >> 1, wc = w & 1;
    int row0 = blockIdx.x * 128;
    int nb = blockIdx.y;
    const __nv_bfloat16* WghB = Wgh + nb * 128 * KD;
    const __nv_bfloat16* WglB = Wgl + nb * 128 * KD;

    if (PASS != 0) {
        const float invM = 1.0f / (float)M_;
        if (t < KD) {
            float mean = g_red[SIN + t] * invM;
            float var  = g_red[SIN + KD + t] * invM - mean * mean;
            float s = rsqrtf(var + EPS_) * gin[t];
            nsc[t] = s; nsh[t] = bin[t] - mean * s;
        }
        __syncthreads();
    } else {
        if (t < 128) { nsc[t] = gin[t]; nsh[t] = bin[t]; }  // att_i, att_j
        __syncthreads();
    }

    float d[2][8][4] = {};
    uint32_t xh_b = smem_to_u32(Xh), xl_b = smem_to_u32(Xl);
    uint32_t wh_b = smem_to_u32(Wh), wl_b = smem_to_u32(Wl);

    for (int kb = 0; kb < KD; kb += 32) {
        #pragma unroll
        for (int v = t; v < 1024; v += 256) {
            int r = v >> 3, k4 = (v & 7) * 4;
            float4 x4 = *(const float4*)&Xg[(row0 + r) * KD + kb + k4];
            float f0, f1, f2, f3;
            if (PASS == 0) {
                f0 = x4.x; f1 = x4.y; f2 = x4.z; f3 = x4.w;
            } else {
                int fc = kb + k4;
                f0 = fmaxf(x4.x * nsc[fc + 0] + nsh[fc + 0], 0.0f);
                f1 = fmaxf(x4.y * nsc[fc + 1] + nsh[fc + 1], 0.0f);
                f2 = fmaxf(x4.z * nsc[fc + 2] + nsh[fc + 2], 0.0f);
                f3 = fmaxf(x4.w * nsc[fc + 3] + nsh[fc + 3], 0.0f);
            }
            ushort_t l0, l1, l2, l3;
            ushort_t h0 = bf_hi(f0, l0), h1 = bf_hi(f1, l1);
            ushort_t h2 = bf_hi(f2, l2), h3 = bf_hi(f3, l3);
            *(ull*)(&Xh[r * 40 + k4]) = pack4(h0, h1, h2, h3);
            *(ull*)(&Xl[r * 40 + k4]) = pack4(l0, l1, l2, l3);
        }
        #pragma unroll
        for (int v = t; v < 512; v += 256) {
            int n = v >> 2, k8 = (v & 3) * 8;
            *(float4*)&Wh[n * 40 + k8] = *(const float4*)&WghB[n * KD + kb + k8];
            *(float4*)&Wl[n * 40 + k8] = *(const float4*)&WglB[n * KD + kb + k8];
        }
        __syncthreads();
        #pragma unroll
        for (int ks = 0; ks < 32; ks += 16) {
            uint32_t ah[2][4], al[2][4];
            uint32_t arow = (uint32_t)(l & 15);
            uint32_t akoff = (uint32_t)((l >> 4) << 3);
            #pragma unroll
            for (int mt = 0; mt < 2; mt++) {
                uint32_t off = ((wr * 32 + mt * 16 + arow) * 40 + ks + akoff) * 2;
                LDSM_X4(ah[mt][0], ah[mt][1], ah[mt][2], ah[mt][3], xh_b + off);
                LDSM_X4(al[mt][0], al[mt][1], al[mt][2], al[mt][3], xl_b + off);
            }
            uint32_t brow = (uint32_t)(((l >> 4) << 3) + (l & 7));
            uint32_t bkoff = (uint32_t)(((l >> 3) & 1) << 3);
            #pragma unroll
            for (int g = 0; g < 4; g++) {
                uint32_t off = ((wc * 64 + g * 16 + brow) * 40 + ks + bkoff) * 2;
                uint32_t bh[4], bl[4];
                LDSM_X4(bh[0], bh[1], bh[2], bh[3], wh_b + off);
                LDSM_X4(bl[0], bl[1], bl[2], bl[3], wl_b + off);
                #pragma unroll
                for (int mt = 0; mt < 2; mt++) {
                    MMA(d[mt][2 * g],     ah[mt], bh[0], bh[1]);
                    MMA(d[mt][2 * g],     ah[mt], bl[0], bl[1]);
                    MMA(d[mt][2 * g],     al[mt], bh[0], bh[1]);
                    MMA(d[mt][2 * g + 1], ah[mt], bh[2], bh[3]);
                    MMA(d[mt][2 * g + 1], ah[mt], bl[2], bl[3]);
                    MMA(d[mt][2 * g + 1], al[mt], bh[2], bh[3]);
                }
            }
        }
        __syncthreads();
    }

    int rbase = row0 + wr * 32 + (l >> 2);
    int cbase = nb * 128 + wc * 64 + (l & 3) * 2;
    #pragma unroll
    for (int mt = 0; mt < 2; mt++) {
        #pragma unroll
        for (int nt = 0; nt < 8; nt++) {
            int col = cbase + nt * 8;
            *(float2*)&outg[(rbase + mt * 16) * OSTR + col] =
                make_float2(d[mt][nt][0], d[mt][nt][1]);
            *(float2*)&outg[(rbase + mt * 16 + 8) * OSTR + col] =
                make_float2(d[mt][nt][2], d[mt][nt][3]);
        }
    }
    if (PASS != 0) {
        #pragma unroll
        for (int nt = 0; nt < 8; nt++) {
            float c0 = d[0][nt][0] + d[0][nt][2] + d[1][nt][0] + d[1][nt][2];
            float c1 = d[0][nt][1] + d[0][nt][3] + d[1][nt][1] + d[1][nt][3];
            float q0 = d[0][nt][0] * d[0][nt][0] + d[0][nt][2] * d[0][nt][2] +
                       d[1][nt][0] * d[1][nt][0] + d[1][nt][2] * d[1][nt][2];
            float q1 = d[0][nt][1] * d[0][nt][1] + d[0][nt][3] * d[0][nt][3] +
                       d[1][nt][1] * d[1][nt][1] + d[1][nt][3] * d[1][nt][3];
            #pragma unroll
            for (int o = 4; o <= 16; o <<= 1) {
                c0 += __shfl_xor_sync(0xffffffffu, c0, o);
                c1 += __shfl_xor_sync(0xffffffffu, c1, o);
                q0 += __shfl_xor_sync(0xffffffffu, q0, o);
                q1 += __shfl_xor_sync(0xffffffffu, q1, o);
            }
            if (l < 4) {
                sbS[wr][wc * 64 + nt * 8 + l * 2]     = c0;
                sbS[wr][wc * 64 + nt * 8 + l * 2 + 1] = c1;
                sbQ[wr][wc * 64 + nt * 8 + l * 2]     = q0;
                sbQ[wr][wc * 64 + nt * 8 + l * 2 + 1] = q1;
            }
        }
        __syncthreads();
        if (t < 128) {
            float S = sbS[0][t] + sbS[1][t] + sbS[2][t] + sbS[3][t];
            float Q = sbQ[0][t] + sbQ[1][t] + sbQ[2][t] + sbQ[3][t];
            atomicAdd(&g_red[SOUT + nb * 128 + t], S);
            atomicAdd(&g_red[SOUT + 256 + nb * 128 + t], Q);
        }
    } else {
        // s_i / s_j epilogue: dot xlin rows with att_i/att_j (in nsc/nsh)
        #pragma unroll
        for (int mt = 0; mt < 2; mt++) {
            float p0 = 0, p1 = 0, pj0 = 0, pj1 = 0;
            #pragma unroll
            for (int nt = 0; nt < 8; nt++) {
                int c = wc * 64 + (l & 3) * 2 + nt * 8;
                p0  += d[mt][nt][0] * nsc[c] + d[mt][nt][1] * nsc[c + 1];
                p1  += d[mt][nt][2] * nsc[c] + d[mt][nt][3] * nsc[c + 1];
                pj0 += d[mt][nt][0] * nsh[c] + d[mt][nt][1] * nsh[c + 1];
                pj1 += d[mt][nt][2] * nsh[c] + d[mt][nt][3] * nsh[c + 1];
            }
            #pragma unroll
            for (int o = 1; o <= 2; o <<= 1) {
                p0  += __shfl_xor_sync(0xffffffffu, p0, o);
                p1  += __shfl_xor_sync(0xffffffffu, p1, o);
                pj0 += __shfl_xor_sync(0xffffffffu, pj0, o);
                pj1 += __shfl_xor_sync(0xffffffffu, pj1, o);
            }
            if ((l & 3) == 0) {
                int rl = wr * 32 + mt * 16 + (l >> 2);
                sbS[wc * 2][rl]     = p0;   // pi, half wc
                sbS[wc * 2 + 1][rl + 8] = 0;  // placeholder避免未初始化? no-op
                sbS[wc * 2][rl + 8] = p1;
                sbQ[wc * 2][rl]     = pj0;
                sbQ[wc * 2][rl + 8] = pj1;
            }
        }
        __syncthreads();
        if (t < 128) {
            int row = row0 + t;
            int n = row & (N_ - 1);
            g_si[row] = sbS[0][t] + sbS[2][t] + g_ei[n];
            g_sj[row] = sbQ[0][t] + sbQ[2][t] + g_ej[n];
        }
    }
}

// ---------------- attention: smem-windowed gather + agg stats ----------------
// grid (4, B_): block = (node group of 128, batch). 512 threads.
// dyn smem: xwin 256x128 f32 (128KB) | combo float2[128*36] | wm ull[128*2]
__global__ __launch_bounds__(512) void k_attn2() {
    extern __shared__ float dsm[];
    float*  xwin  = dsm;                       // 32768 floats
    float2* combo = (float2*)(dsm + 32768);    // 128*36 float2 = 9216 floats
    ull*    wm    = (ull*)(dsm + 32768 + 9216);  // 128*2 ull = 512 floats

    int t = threadIdx.x, lane = t & 31, w = t >> 5;  // 16 warps
    int b = blockIdx.y, i0 = blockIdx.x * 128;

    // ---- precompute alpha, src, window masks (warp per 8 nodes) ----
    #pragma unroll
    for (int q = 0; q < 8; q++) {
        int mi = w * 8 + q;
        int i = i0 + mi;
        int m = b * N_ + i;
        int src = g_topk[i * K_ + lane];
        float sim = g_si[m];
        float v = sim + g_sj[b * N_ + src];
        float lg = v > 0.0f ? v : 0.2f * v;
        bool valid = (src != i);
        if (!valid) lg = -1e30f;
        float vs = sim + g_sj[m];
        float lgs = vs > 0.0f ? vs : 0.2f * vs;
        float mx = lg;
        #pragma unroll
        for (int o = 16; o > 0; o >>= 1)
            mx = fmaxf(mx, __shfl_xor_sync(0xffffffffu, mx, o));
        mx = fmaxf(mx, lgs);
        float e = valid ? expf(lg - mx) : 0.0f;
        float es = expf(lgs - mx);
        float den = e;
        #pragma unroll
        for (int o = 16; o > 0; o >>= 1)
            den += __shfl_xor_sync(0xffffffffu, den, o);
        den += es;
        combo[mi * 36 + lane] = make_float2(e / den, __int_as_float(src));
        unsigned bal = __ballot_sync(0xffffffffu, src < 256);
        if (lane == 0) {
            combo[mi * 36 + 32] = make_float2(es / den, __int_as_float(i));
            wm[mi * 2 + 0] = (ull)bal | ((ull)(i < 256 ? 1 : 0) << 32);
            wm[mi * 2 + 1] = (ull)(~bal) | ((ull)(i >= 256 ? 1 : 0) << 32);
        }
    }

    float acc[8][4] = {};
    for (int win = 0; win < 2; win++) {
        __syncthreads();
        // load window: rows [win*256, win*256+256) of batch b
        const float4* srcp = (const float4*)&g_xlin[(b * N_ + win * 256) * D_];
        #pragma unroll
        for (int v = t; v < 8192; v += 512)
            ((float4*)xwin)[v] = srcp[v];
        __syncthreads();
        #pragma unroll
        for (int q = 0; q < 8; q++) {
            int mi = w * 8 + q;
            ull mk = wm[mi * 2 + win];
            while (mk) {
                int k = __ffsll((long long)mk) - 1;
                mk &= mk - 1;
                float2 cv = combo[mi * 36 + k];
                int src = __float_as_int(cv.y);
                float a = cv.x;
                float4 xv = *(float4*)&xwin[(src & 255) * D_ + lane * 4];
                acc[q][0] += a * xv.x; acc[q][1] += a * xv.y;
                acc[q][2] += a * xv.z; acc[q][3] += a * xv.w;
            }
        }
    }
    __syncthreads();
    // write agg + fused stats
    float s[4] = {}, qd[4] = {};
    #pragma unroll
    for (int q = 0; q < 8; q++) {
        int m = b * N_ + i0 + w * 8 + q;
        *(float4*)&g_agg[m * D_ + lane * 4] =
            make_float4(acc[q][0], acc[q][1], acc[q][2], acc[q][3]);
        #pragma unroll
        for (int c = 0; c < 4; c++) { s[c] += acc[q][c]; qd[c] += acc[q][c] * acc[q][c]; }
    }
    float* sS = dsm + 32768;          // reuse combo region (done with it)
    float* sQ = dsm + 32768 + 2048;
    #pragma unroll
    for (int c = 0; c < 4; c++) {
        sS[w * 128 + lane * 4 + c] = s[c];
        sQ[w * 128 + lane * 4 + c] = qd[c];
    }
    __syncthreads();
    if (t < 128) {
        float S = 0, Q = 0;
        #pragma unroll
        for (int g = 0; g < 16; g++) { S += sS[g * 128 + t]; Q += sQ[g * 128 + t]; }
        atomicAdd(&g_red[t], S);
        atomicAdd(&g_red[128 + t], Q);
    }
}

// ---------------- gcn = relu(bn(agg)); h = gcn*emb + h stats ----------------
__global__ __launch_bounds__(128) void k_h(const float* __restrict__ emb,
                                           const float* __restrict__ g0,
                                           const float* __restrict__ b0) {
    int d = threadIdx.x;
    int r0 = blockIdx.x * 64;
    const float invM = 1.0f / (float)M_;
    float mean = g_red[d] * invM;
    float var  = g_red[D_ + d] * invM - mean * mean;
    float sc = rsqrtf(var + EPS_) * g0[d];
    float sh = b0[d] - mean * sc;
    float ssum = 0.0f, ssq = 0.0f;
    for (int r = r0; r < r0 + 64; r++) {
        float a = g_agg[r * D_ + d];
        float gcn = fmaxf(a * sc + sh, 0.0f);
        float h = gcn * emb[(r & (N_ - 1)) * D_ + d];
        g_h[r * D_ + d] = h;
        ssum += h; ssq += h * h;
    }
    atomicAdd(&g_red[256 + d], ssum);
    atomicAdd(&g_red[384 + d], ssq);
}

// ---------------- final: out = relu(bn(o2)) @ W3 + b3 ----------------
__global__ __launch_bounds__(256) void k_out(const float* __restrict__ W3,
                                             const float* __restrict__ b3,
                                             const float* __restrict__ g2,
                                             const float* __restrict__ b2v,
                                             float* __restrict__ out) {
    __shared__ float nsc[256], nsh[256], w[256];
    int t = threadIdx.x;
    const float invM = 1.0f / (float)M_;
    {
        float mean = g_red[1024 + t] * invM;
        float var  = g_red[1280 + t] * invM - mean * mean;
        float s = rsqrtf(var + EPS_) * g2[t];
        nsc[t] = s; nsh[t] = b2v[t] - mean * s; w[t] = W3[t];
    }
    __syncthreads();
    int warp = t >> 5, lane = t & 31;
    int m = blockIdx.x * 8 + warp;
    float acc = 0.0f;
    #pragma unroll
    for (int f = lane; f < 256; f += 32) {
        float v = g_o2[m * 256 + f];
        acc += fmaxf(v * nsc[f] + nsh[f], 0.0f) * w[f];
    }
    for (int o = 16; o > 0; o >>= 1)
        acc += __shfl_xor_sync(0xffffffffu, acc, o);
    if (lane == 0) out[m] = acc + b3[0];
}

// ---------------- launch ----------------
extern "C" void kernel_launch(void* const* d_in, const int* in_sizes, int n_in,
                              void* d_out, int out_size) {
    const float* data   = (const float*)d_in[0];
    const float* emb    = (const float*)d_in[1];
    const float* lin_W  = (const float*)d_in[2];
    const float* att_i  = (const float*)d_in[3];
    const float* att_j  = (const float*)d_in[4];
    const float* aem_i  = (const float*)d_in[5];
    const float* aem_j  = (const float*)d_in[6];
    // d_in[7] = gnn_bias : cancels exactly under BN
    const float* gnn_g  = (const float*)d_in[8];
    const float* gnn_b  = (const float*)d_in[9];
    const float* bno_g  = (const float*)d_in[10];
    const float* bno_b  = (const float*)d_in[11];
    const float* W1     = (const float*)d_in[12];
    // d_in[13] = b1 : cancels
    const float* bn1_g  = (const float*)d_in[14];
    const float* bn1_b  = (const float*)d_in[15];
    const float* W2     = (const float*)d_in[16];
    // d_in[17] = b2 : cancels
    const float* bn2_g  = (const float*)d_in[18];
    const float* bn2_b  = (const float*)d_in[19];
    const float* W3     = (const float*)d_in[20];
    const float* b3     = (const float*)d_in[21];
    float* out = (float*)d_out;

    const int ATTN_SMEM = (32768 + 9216 + 512) * 4;  // 169984 B
    cudaFuncSetAttribute(k_attn2, cudaFuncAttributeMaxDynamicSharedMemorySize,
                         ATTN_SMEM);

    k_zero<<<6, 256>>>();
    k_prepW<<<112, 1024>>>(lin_W, W1, W2);
    k_pre<<<N_, 128>>>(emb, aem_i, aem_j);
    k_gram<<<dim3(8, 8), 256>>>(emb);
    k_sel<<<64, 256>>>();
    k_gemm<0><<<dim3(M_ / 128, 1), 256>>>(data, att_i, att_j);
    k_attn2<<<dim3(4, B_), 512, ATTN_SMEM>>>();
    k_h<<<M_ / 64, 128>>>(emb, gnn_g, gnn_b);
    k_gemm<1><<<dim3(M_ / 128, 2), 256>>>(nullptr, bno_g, bno_b);
    k_gemm<2><<<dim3(M_ / 128, 2), 256>>>(nullptr, bn1_g, bn1_b);
    k_out<<<M_ / 8, 256>>>(W3, b3, bn2_g, bn2_b, out);
}

// round 8
// speedup vs baseline: 2.7712x; 1.0670x over previous
#include <cuda_runtime.h>
#include <cuda_bf16.h>
#include <math.h>
#include <stdint.h>

#define B_ 64
#define N_ 512
#define D_ 128
#define K_ 32
#define M_ (B_ * N_)
#define EPS_ 1e-5f

typedef unsigned long long ull;
typedef unsigned short ushort_t;

// ---------------- device scratch ----------------
__device__ float g_xlin[M_ * D_];
__device__ float g_si[M_];
__device__ float g_sj[M_];
__device__ float g_ei[N_];
__device__ float g_ej[N_];
__device__ float g_nrm[N_];
__device__ float g_cos[N_ * N_];
__device__ int   g_topk[N_ * K_];
__device__ float g_agg[M_ * D_];
__device__ float g_h[M_ * D_];
__device__ float g_o1[M_ * 256];
__device__ float g_o2[M_ * 256];
// W images: [n][k] row-major bf16, hi/lo split
__device__ __nv_bfloat16 g_Wh0[128 * 128], g_Wl0[128 * 128];
__device__ __nv_bfloat16 g_Wh1[256 * 128], g_Wl1[256 * 128];
__device__ __nv_bfloat16 g_Wh2[256 * 256], g_Wl2[256 * 256];
// stats: [0]=agg sum(128) [128]=agg sq [256]=h sum [384]=h sq
//        [512]=o1 sum(256) [768]=o1 sq [1024]=o2 sum [1280]=o2 sq
__device__ float g_red[1536];

// ---------------- helpers ----------------
__device__ __forceinline__ uint32_t smem_to_u32(const void* p) {
    uint32_t a;
    asm("{ .reg .u64 t; cvta.to.shared.u64 t, %1; cvt.u32.u64 %0, t; }"
        : "=r"(a) : "l"(p));
    return a;
}
__device__ __forceinline__ ushort_t bf_hi(float f, ushort_t& lo) {
    __nv_bfloat16 h = __float2bfloat16(f);
    float r = f - __bfloat162float(h);
    lo = __bfloat16_as_ushort(__float2bfloat16(r));
    return __bfloat16_as_ushort(h);
}
__device__ __forceinline__ ull pack4(ushort_t a, ushort_t b, ushort_t c, ushort_t d) {
    return (ull)a | ((ull)b << 16) | ((ull)c << 32) | ((ull)d << 48);
}
#define LDSM_X4(r0, r1, r2, r3, addr) \
    asm volatile("ldmatrix.sync.aligned.m8n8.x4.shared.b16 {%0,%1,%2,%3}, [%4];" \
                 : "=r"(r0), "=r"(r1), "=r"(r2), "=r"(r3) : "r"(addr))
#define MMA(dd, aa, b0v, b1v) \
    asm volatile("mma.sync.aligned.m16n8k16.row.col.f32.bf16.bf16.f32 " \
                 "{%0,%1,%2,%3}, {%4,%5,%6,%7}, {%8,%9}, {%0,%1,%2,%3};" \
                 : "+f"((dd)[0]), "+f"((dd)[1]), "+f"((dd)[2]), "+f"((dd)[3]) \
                 : "r"((aa)[0]), "r"((aa)[1]), "r"((aa)[2]), "r"((aa)[3]), \
                   "r"(b0v), "r"(b1v))

// ---------------- init: zero stats + W prep + per-node norm/ei/ej -----------
// grid 256 x 256 threads. All three tasks are independent.
__global__ __launch_bounds__(256) void k_init(const float* __restrict__ linW,
                                              const float* __restrict__ W1,
                                              const float* __restrict__ W2,
                                              const float* __restrict__ emb,
                                              const float* __restrict__ aei,
                                              const float* __restrict__ aej) {
    int b = blockIdx.x, t = threadIdx.x;
    int gid = b * 256 + t;
    if (gid < 1536) g_red[gid] = 0.0f;
    // --- W prep: 114688 elements, stride 65536 ---
    for (int id = gid; id < 114688; id += 65536) {
        if (id < 16384) {
            int n = id >> 7, k = id & 127;
            ushort_t lo; ushort_t hi = bf_hi(linW[k * 128 + n], lo);
            g_Wh0[n * 128 + k] = __ushort_as_bfloat16(hi);
            g_Wl0[n * 128 + k] = __ushort_as_bfloat16(lo);
        } else if (id < 49152) {
            int e = id - 16384;
            int n = e >> 7, k = e & 127;
            ushort_t lo; ushort_t hi = bf_hi(W1[k * 256 + n], lo);
            g_Wh1[n * 128 + k] = __ushort_as_bfloat16(hi);
            g_Wl1[n * 128 + k] = __ushort_as_bfloat16(lo);
        } else {
            int e = id - 49152;
            int n = e >> 8, k = e & 255;
            ushort_t lo; ushort_t hi = bf_hi(W2[k * 256 + n], lo);
            g_Wh2[n * 256 + k] = __ushort_as_bfloat16(hi);
            g_Wl2[n * 256 + k] = __ushort_as_bfloat16(lo);
        }
    }
    // --- pre: blocks 0..63, warp per node ---
    if (b < 64) {
        int w = t >> 5, lane = t & 31;
        int n = b * 8 + w;
        float4 v4 = *(const float4*)&emb[n * D_ + lane * 4];
        float4 ai4 = *(const float4*)&aei[lane * 4];
        float4 aj4 = *(const float4*)&aej[lane * 4];
        float s2 = v4.x * v4.x + v4.y * v4.y + v4.z * v4.z + v4.w * v4.w;
        float pi = v4.x * ai4.x + v4.y * ai4.y + v4.z * ai4.z + v4.w * ai4.w;
        float pj = v4.x * aj4.x + v4.y * aj4.y + v4.z * aj4.z + v4.w * aj4.w;
        #pragma unroll
        for (int o = 16; o > 0; o >>= 1) {
            s2 += __shfl_xor_sync(0xffffffffu, s2, o);
            pi += __shfl_xor_sync(0xffffffffu, pi, o);
            pj += __shfl_xor_sync(0xffffffffu, pj, o);
        }
        if (lane == 0) {
            g_nrm[n] = sqrtf(s2);
            g_ei[n] = pi;
            g_ej[n] = pj;
        }
    }
}

// ---------------- cosine Gram matrix: 32x64 tiles, 128 blocks ----------------
__global__ __launch_bounds__(256) void k_gram(const float* __restrict__ emb) {
    __shared__ float Ash[128][32];
    __shared__ float Bsh[128][64];
    int t = threadIdx.x;
    int i0 = blockIdx.x * 32, j0 = blockIdx.y * 64;
    // load A: 32 rows x 128 k -> k-major; 4096 floats / 256 = 4 float4 each
    {
        int r = t & 31, kq0 = t >> 5;  // 8 k-quads, step 8
        #pragma unroll
        for (int q = 0; q < 4; q++) {
            int kq = kq0 + q * 8;
            float4 a = *(const float4*)&emb[(i0 + r) * 128 + kq * 4];
            Ash[kq * 4 + 0][r] = a.x; Ash[kq * 4 + 1][r] = a.y;
            Ash[kq * 4 + 2][r] = a.z; Ash[kq * 4 + 3][r] = a.w;
        }
    }
    {
        int r = t & 63, kq0 = t >> 6;  // 4 k-quads, step 4
        #pragma unroll
        for (int q = 0; q < 8; q++) {
            int kq = kq0 + q * 4;
            float4 b = *(const float4*)&emb[(j0 + r) * 128 + kq * 4];
            Bsh[kq * 4 + 0][r] = b.x; Bsh[kq * 4 + 1][r] = b.y;
            Bsh[kq * 4 + 2][r] = b.z; Bsh[kq * 4 + 3][r] = b.w;
        }
    }
    __syncthreads();
    int tr = t >> 4, tc = t & 15;   // 16 row-groups x 16 col-groups
    float acc[2][4] = {};
    #pragma unroll 4
    for (int k = 0; k < 128; k++) {
        float2 av = *(float2*)&Ash[k][tr * 2];
        float4 bv = *(float4*)&Bsh[k][tc * 4];
        acc[0][0] += av.x * bv.x; acc[0][1] += av.x * bv.y;
        acc[0][2] += av.x * bv.z; acc[0][3] += av.x * bv.w;
        acc[1][0] += av.y * bv.x; acc[1][1] += av.y * bv.y;
        acc[1][2] += av.y * bv.z; acc[1][3] += av.y * bv.w;
    }
    float invi[2], invj[4];
    #pragma unroll
    for (int q = 0; q < 2; q++) invi[q] = 1.0f / g_nrm[i0 + tr * 2 + q];
    #pragma unroll
    for (int q = 0; q < 4; q++) invj[q] = 1.0f / g_nrm[j0 + tc * 4 + q];
    #pragma unroll
    for (int rr = 0; rr < 2; rr++) {
        float s = invi[rr];
        *(float4*)&g_cos[(i0 + tr * 2 + rr) * N_ + j0 + tc * 4] =
            make_float4(acc[rr][0] * s * invj[0], acc[rr][1] * s * invj[1],
                        acc[rr][2] * s * invj[2], acc[rr][3] * s * invj[3]);
    }
}

// ---------------- topk selection: one warp per row ----------------
__global__ __launch_bounds__(256) void k_sel() {
    __shared__ float sv[8][512];
    int t = threadIdx.x, w = t >> 5, lane = t & 31;
    int i = blockIdx.x * 8 + w;
    float* v = sv[w];
    #pragma unroll
    for (int q = 0; q < 16; q++)
        v[q * 32 + lane] = g_cos[i * N_ + q * 32 + lane];
    float lv = v[lane]; int li = 0;
    #pragma unroll
    for (int q = 1; q < 16; q++) {
        float x = v[q * 32 + lane];
        if (x > lv) { lv = x; li = q; }
    }
    for (int k = 0; k < K_; k++) {
        float bv = lv;
        int bj = li * 32 + lane;
        #pragma unroll
        for (int o = 16; o > 0; o >>= 1) {
            float ov = __shfl_xor_sync(0xffffffffu, bv, o);
            int oj = __shfl_xor_sync(0xffffffffu, bj, o);
            if (ov > bv || (ov == bv && oj < bj)) { bv = ov; bj = oj; }
        }
        if (lane == 0) g_topk[i * K_ + k] = bj;
        if ((bj & 31) == lane) {
            v[bj] = -2.0f;
            lv = v[lane]; li = 0;
            #pragma unroll
            for (int q = 1; q < 16; q++) {
                float x = v[q * 32 + lane];
                if (x > lv) { lv = x; li = q; }
            }
        }
        __syncwarp();
    }
}

// ---------------- unified HMMA GEMM (3-term bf16 split) ----------------
// PASS 0: g_xlin = data @ linW ; epilogue computes g_si/g_sj (gin=att_i, bin=att_j)
// PASS 1: g_o1 = relu(bn(g_h)) @ W1   ; PASS 2: g_o2 = relu(bn(g_o1)) @ W2
template <int PASS>
__global__ __launch_bounds__(256) void k_gemm(const float* __restrict__ Xext,
                                              const float* __restrict__ gin,
                                              const float* __restrict__ bin) {
    constexpr int KD   = (PASS == 2) ? 256 : 128;
    constexpr int OSTR = (PASS == 0) ? 128 : 256;
    constexpr int SIN  = (PASS == 1) ? 256 : 512;
    constexpr int SOUT = (PASS == 1) ? 512 : 1024;

    __shared__ __align__(16) __nv_bfloat16 Xh[128 * 40];
    __shared__ __align__(16) __nv_bfloat16 Xl[128 * 40];
    __shared__ __align__(16) __nv_bfloat16 Wh[128 * 40];
    __shared__ __align__(16) __nv_bfloat16 Wl[128 * 40];
    __shared__ float nsc[256], nsh[256];
    __shared__ float sbS[4][128], sbQ[4][128];

    const float* __restrict__ Xg =
        (PASS == 0) ? Xext : ((PASS == 1) ? g_h : g_o1);
    float* __restrict__ outg =
        (PASS == 0) ? g_xlin : ((PASS == 1) ? g_o1 : g_o2);
    const __nv_bfloat16* Wgh = (PASS == 0) ? g_Wh0 : ((PASS == 1) ? g_Wh1 : g_Wh2);
    const __nv_bfloat16* Wgl = (PASS == 0) ? g_Wl0 : ((PASS == 1) ? g_Wl1 : g_Wl2);

    int t = threadIdx.x, l = t & 31, w = t >> 5;
    int wr = w >> 1, wc = w & 1;
    int row0 = blockIdx.x * 128;
    int nb = blockIdx.y;
    const __nv_bfloat16* WghB = Wgh + nb * 128 * KD;
    const __nv_bfloat16* WglB = Wgl + nb * 128 * KD;

    if (PASS != 0) {
        const float invM = 1.0f / (float)M_;
        if (t < KD) {
            float mean = g_red[SIN + t] * invM;
            float var  = g_red[SIN + KD + t] * invM - mean * mean;
            float s = rsqrtf(var + EPS_) * gin[t];
            nsc[t] = s; nsh[t] = bin[t] - mean * s;
        }
        __syncthreads();
    } else {
        if (t < 128) { nsc[t] = gin[t]; nsh[t] = bin[t]; }  // att_i, att_j
        __syncthreads();
    }

    float d[2][8][4] = {};
    uint32_t xh_b = smem_to_u32(Xh), xl_b = smem_to_u32(Xl);
    uint32_t wh_b = smem_to_u32(Wh), wl_b = smem_to_u32(Wl);

    for (int kb = 0; kb < KD; kb += 32) {
        #pragma unroll
        for (int v = t; v < 1024; v += 256) {
            int r = v >> 3, k4 = (v & 7) * 4;
            float4 x4 = *(const float4*)&Xg[(row0 + r) * KD + kb + k4];
            float f0, f1, f2, f3;
            if (PASS == 0) {
                f0 = x4.x; f1 = x4.y; f2 = x4.z; f3 = x4.w;
            } else {
                int fc = kb + k4;
                f0 = fmaxf(x4.x * nsc[fc + 0] + nsh[fc + 0], 0.0f);
                f1 = fmaxf(x4.y * nsc[fc + 1] + nsh[fc + 1], 0.0f);
                f2 = fmaxf(x4.z * nsc[fc + 2] + nsh[fc + 2], 0.0f);
                f3 = fmaxf(x4.w * nsc[fc + 3] + nsh[fc + 3], 0.0f);
            }
            ushort_t l0, l1, l2, l3;
            ushort_t h0 = bf_hi(f0, l0), h1 = bf_hi(f1, l1);
            ushort_t h2 = bf_hi(f2, l2), h3 = bf_hi(f3, l3);
            *(ull*)(&Xh[r * 40 + k4]) = pack4(h0, h1, h2, h3);
            *(ull*)(&Xl[r * 40 + k4]) = pack4(l0, l1, l2, l3);
        }
        #pragma unroll
        for (int v = t; v < 512; v += 256) {
            int n = v >> 2, k8 = (v & 3) * 8;
            *(float4*)&Wh[n * 40 + k8] = *(const float4*)&WghB[n * KD + kb + k8];
            *(float4*)&Wl[n * 40 + k8] = *(const float4*)&WglB[n * KD + kb + k8];
        }
        __syncthreads();
        #pragma unroll
        for (int ks = 0; ks < 32; ks += 16) {
            uint32_t ah[2][4], al[2][4];
            uint32_t arow = (uint32_t)(l & 15);
            uint32_t akoff = (uint32_t)((l >> 4) << 3);
            #pragma unroll
            for (int mt = 0; mt < 2; mt++) {
                uint32_t off = ((wr * 32 + mt * 16 + arow) * 40 + ks + akoff) * 2;
                LDSM_X4(ah[mt][0], ah[mt][1], ah[mt][2], ah[mt][3], xh_b + off);
                LDSM_X4(al[mt][0], al[mt][1], al[mt][2], al[mt][3], xl_b + off);
            }
            uint32_t brow = (uint32_t)(((l >> 4) << 3) + (l & 7));
            uint32_t bkoff = (uint32_t)(((l >> 3) & 1) << 3);
            #pragma unroll
            for (int g = 0; g < 4; g++) {
                uint32_t off = ((wc * 64 + g * 16 + brow) * 40 + ks + bkoff) * 2;
                uint32_t bh[4], bl[4];
                LDSM_X4(bh[0], bh[1], bh[2], bh[3], wh_b + off);
                LDSM_X4(bl[0], bl[1], bl[2], bl[3], wl_b + off);
                #pragma unroll
                for (int mt = 0; mt < 2; mt++) {
                    MMA(d[mt][2 * g],     ah[mt], bh[0], bh[1]);
                    MMA(d[mt][2 * g],     ah[mt], bl[0], bl[1]);
                    MMA(d[mt][2 * g],     al[mt], bh[0], bh[1]);
                    MMA(d[mt][2 * g + 1], ah[mt], bh[2], bh[3]);
                    MMA(d[mt][2 * g + 1], ah[mt], bl[2], bl[3]);
                    MMA(d[mt][2 * g + 1], al[mt], bh[2], bh[3]);
                }
            }
        }
        __syncthreads();
    }

    int rbase = row0 + wr * 32 + (l >> 2);
    int cbase = nb * 128 + wc * 64 + (l & 3) * 2;
    #pragma unroll
    for (int mt = 0; mt < 2; mt++) {
        #pragma unroll
        for (int nt = 0; nt < 8; nt++) {
            int col = cbase + nt * 8;
            *(float2*)&outg[(rbase + mt * 16) * OSTR + col] =
                make_float2(d[mt][nt][0], d[mt][nt][1]);
            *(float2*)&outg[(rbase + mt * 16 + 8) * OSTR + col] =
                make_float2(d[mt][nt][2], d[mt][nt][3]);
        }
    }
    if (PASS != 0) {
        #pragma unroll
        for (int nt = 0; nt < 8; nt++) {
            float c0 = d[0][nt][0] + d[0][nt][2] + d[1][nt][0] + d[1][nt][2];
            float c1 = d[0][nt][1] + d[0][nt][3] + d[1][nt][1] + d[1][nt][3];
            float q0 = d[0][nt][0] * d[0][nt][0] + d[0][nt][2] * d[0][nt][2] +
                       d[1][nt][0] * d[1][nt][0] + d[1][nt][2] * d[1][nt][2];
            float q1 = d[0][nt][1] * d[0][nt][1] + d[0][nt][3] * d[0][nt][3] +
                       d[1][nt][1] * d[1][nt][1] + d[1][nt][3] * d[1][nt][3];
            #pragma unroll
            for (int o = 4; o <= 16; o <<= 1) {
                c0 += __shfl_xor_sync(0xffffffffu, c0, o);
                c1 += __shfl_xor_sync(0xffffffffu, c1, o);
                q0 += __shfl_xor_sync(0xffffffffu, q0, o);
                q1 += __shfl_xor_sync(0xffffffffu, q1, o);
            }
            if (l < 4) {
                sbS[wr][wc * 64 + nt * 8 + l * 2]     = c0;
                sbS[wr][wc * 64 + nt * 8 + l * 2 + 1] = c1;
                sbQ[wr][wc * 64 + nt * 8 + l * 2]     = q0;
                sbQ[wr][wc * 64 + nt * 8 + l * 2 + 1] = q1;
            }
        }
        __syncthreads();
        if (t < 128) {
            float S = sbS[0][t] + sbS[1][t] + sbS[2][t] + sbS[3][t];
            float Q = sbQ[0][t] + sbQ[1][t] + sbQ[2][t] + sbQ[3][t];
            atomicAdd(&g_red[SOUT + nb * 128 + t], S);
            atomicAdd(&g_red[SOUT + 256 + nb * 128 + t], Q);
        }
    } else {
        // s_i / s_j epilogue
        #pragma unroll
        for (int mt = 0; mt < 2; mt++) {
            float p0 = 0, p1 = 0, pj0 = 0, pj1 = 0;
            #pragma unroll
            for (int nt = 0; nt < 8; nt++) {
                int c = wc * 64 + (l & 3) * 2 + nt * 8;
                p0  += d[mt][nt][0] * nsc[c] + d[mt][nt][1] * nsc[c + 1];
                p1  += d[mt][nt][2] * nsc[c] + d[mt][nt][3] * nsc[c + 1];
                pj0 += d[mt][nt][0] * nsh[c] + d[mt][nt][1] * nsh[c + 1];
                pj1 += d[mt][nt][2] * nsh[c] + d[mt][nt][3] * nsh[c + 1];
            }
            #pragma unroll
            for (int o = 1; o <= 2; o <<= 1) {
                p0  += __shfl_xor_sync(0xffffffffu, p0, o);
                p1  += __shfl_xor_sync(0xffffffffu, p1, o);
                pj0 += __shfl_xor_sync(0xffffffffu, pj0, o);
                pj1 += __shfl_xor_sync(0xffffffffu, pj1, o);
            }
            if ((l & 3) == 0) {
                int rl = wr * 32 + mt * 16 + (l >> 2);
                sbS[wc * 2][rl]     = p0;
                sbS[wc * 2][rl + 8] = p1;
                sbQ[wc * 2][rl]     = pj0;
                sbQ[wc * 2][rl + 8] = pj1;
            }
        }
        __syncthreads();
        if (t < 128) {
            int row = row0 + t;
            int n = row & (N_ - 1);
            g_si[row] = sbS[0][t] + sbS[2][t] + g_ei[n];
            g_sj[row] = sbQ[0][t] + sbQ[2][t] + g_ej[n];
        }
    }
}

// ---------------- attention: smem-windowed gather + agg stats ----------------
__global__ __launch_bounds__(512) void k_attn2() {
    extern __shared__ float dsm[];
    float*  xwin  = dsm;                       // 32768 floats
    float2* combo = (float2*)(dsm + 32768);    // 128*36 float2
    ull*    wm    = (ull*)(dsm + 32768 + 9216);

    int t = threadIdx.x, lane = t & 31, w = t >> 5;  // 16 warps
    int b = blockIdx.y, i0 = blockIdx.x * 128;

    #pragma unroll
    for (int q = 0; q < 8; q++) {
        int mi = w * 8 + q;
        int i = i0 + mi;
        int m = b * N_ + i;
        int src = g_topk[i * K_ + lane];
        float sim = g_si[m];
        float v = sim + g_sj[b * N_ + src];
        float lg = v > 0.0f ? v : 0.2f * v;
        bool valid = (src != i);
        if (!valid) lg = -1e30f;
        float vs = sim + g_sj[m];
        float lgs = vs > 0.0f ? vs : 0.2f * vs;
        float mx = lg;
        #pragma unroll
        for (int o = 16; o > 0; o >>= 1)
            mx = fmaxf(mx, __shfl_xor_sync(0xffffffffu, mx, o));
        mx = fmaxf(mx, lgs);
        float e = valid ? expf(lg - mx) : 0.0f;
        float es = expf(lgs - mx);
        float den = e;
        #pragma unroll
        for (int o = 16; o > 0; o >>= 1)
            den += __shfl_xor_sync(0xffffffffu, den, o);
        den += es;
        combo[mi * 36 + lane] = make_float2(e / den, __int_as_float(src));
        unsigned bal = __ballot_sync(0xffffffffu, src < 256);
        if (lane == 0) {
            combo[mi * 36 + 32] = make_float2(es / den, __int_as_float(i));
            wm[mi * 2 + 0] = (ull)bal | ((ull)(i < 256 ? 1 : 0) << 32);
            wm[mi * 2 + 1] = (ull)(~bal) | ((ull)(i >= 256 ? 1 : 0) << 32);
        }
    }

    float acc[8][4] = {};
    for (int win = 0; win < 2; win++) {
        __syncthreads();
        const float4* srcp = (const float4*)&g_xlin[(b * N_ + win * 256) * D_];
        #pragma unroll
        for (int v = t; v < 8192; v += 512)
            ((float4*)xwin)[v] = srcp[v];
        __syncthreads();
        #pragma unroll
        for (int q = 0; q < 8; q++) {
            int mi = w * 8 + q;
            ull mk = wm[mi * 2 + win];
            while (mk) {
                int k = __ffsll((long long)mk) - 1;
                mk &= mk - 1;
                float2 cv = combo[mi * 36 + k];
                int src = __float_as_int(cv.y);
                float a = cv.x;
                float4 xv = *(float4*)&xwin[(src & 255) * D_ + lane * 4];
                acc[q][0] += a * xv.x; acc[q][1] += a * xv.y;
                acc[q][2] += a * xv.z; acc[q][3] += a * xv.w;
            }
        }
    }
    __syncthreads();
    float s[4] = {}, qd[4] = {};
    #pragma unroll
    for (int q = 0; q < 8; q++) {
        int m = b * N_ + i0 + w * 8 + q;
        *(float4*)&g_agg[m * D_ + lane * 4] =
            make_float4(acc[q][0], acc[q][1], acc[q][2], acc[q][3]);
        #pragma unroll
        for (int c = 0; c < 4; c++) { s[c] += acc[q][c]; qd[c] += acc[q][c] * acc[q][c]; }
    }
    float* sS = dsm + 32768;
    float* sQ = dsm + 32768 + 2048;
    #pragma unroll
    for (int c = 0; c < 4; c++) {
        sS[w * 128 + lane * 4 + c] = s[c];
        sQ[w * 128 + lane * 4 + c] = qd[c];
    }
    __syncthreads();
    if (t < 128) {
        float S = 0, Q = 0;
        #pragma unroll
        for (int g = 0; g < 16; g++) { S += sS[g * 128 + t]; Q += sQ[g * 128 + t]; }
        atomicAdd(&g_red[t], S);
        atomicAdd(&g_red[128 + t], Q);
    }
}

// ---------------- gcn = relu(bn(agg)); h = gcn*emb + h stats ----------------
// 512 blocks x 256 threads; warp handles 8 rows, lane = 4 channels (float4).
__global__ __launch_bounds__(256) void k_h(const float* __restrict__ emb,
                                           const float* __restrict__ g0,
                                           const float* __restrict__ b0) {
    __shared__ float sS[8][128], sQ[8][128];
    int t = threadIdx.x, w = t >> 5, lane = t & 31;
    int r0 = blockIdx.x * 64 + w * 8;
    const float invM = 1.0f / (float)M_;
    int d4 = lane * 4;
    float4 sm = *(float4*)&g_red[d4];
    float4 sq = *(float4*)&g_red[D_ + d4];
    float4 gg = *(const float4*)&g0[d4];
    float4 bb = *(const float4*)&b0[d4];
    float mean0 = sm.x * invM, mean1 = sm.y * invM, mean2 = sm.z * invM, mean3 = sm.w * invM;
    float sc0 = rsqrtf(sq.x * invM - mean0 * mean0 + EPS_) * gg.x;
    float sc1 = rsqrtf(sq.y * invM - mean1 * mean1 + EPS_) * gg.y;
    float sc2 = rsqrtf(sq.z * invM - mean2 * mean2 + EPS_) * gg.z;
    float sc3 = rsqrtf(sq.w * invM - mean3 * mean3 + EPS_) * gg.w;
    float sh0 = bb.x - mean0 * sc0, sh1 = bb.y - mean1 * sc1;
    float sh2 = bb.z - mean2 * sc2, sh3 = bb.w - mean3 * sc3;
    float S[4] = {}, Q[4] = {};
    #pragma unroll
    for (int r = 0; r < 8; r++) {
        int row = r0 + r;
        float4 a = *(float4*)&g_agg[row * D_ + d4];
        float4 e = *(const float4*)&emb[(row & (N_ - 1)) * D_ + d4];
        float h0 = fmaxf(a.x * sc0 + sh0, 0.0f) * e.x;
        float h1 = fmaxf(a.y * sc1 + sh1, 0.0f) * e.y;
        float h2 = fmaxf(a.z * sc2 + sh2, 0.0f) * e.z;
        float h3 = fmaxf(a.w * sc3 + sh3, 0.0f) * e.w;
        *(float4*)&g_h[row * D_ + d4] = make_float4(h0, h1, h2, h3);
        S[0] += h0; S[1] += h1; S[2] += h2; S[3] += h3;
        Q[0] += h0 * h0; Q[1] += h1 * h1; Q[2] += h2 * h2; Q[3] += h3 * h3;
    }
    #pragma unroll
    for (int c = 0; c < 4; c++) { sS[w][d4 + c] = S[c]; sQ[w][d4 + c] = Q[c]; }
    __syncthreads();
    if (t < 128) {
        float Ss = 0, Qs = 0;
        #pragma unroll
        for (int g = 0; g < 8; g++) { Ss += sS[g][t]; Qs += sQ[g][t]; }
        atomicAdd(&g_red[256 + t], Ss);
        atomicAdd(&g_red[384 + t], Qs);
    }
}

// ---------------- final: out = relu(bn(o2)) @ W3 + b3 ----------------
__global__ __launch_bounds__(256) void k_out(const float* __restrict__ W3,
                                             const float* __restrict__ b3,
                                             const float* __restrict__ g2,
                                             const float* __restrict__ b2v,
                                             float* __restrict__ out) {
    __shared__ float nsc[256], nsh[256], w[256];
    int t = threadIdx.x;
    const float invM = 1.0f / (float)M_;
    {
        float mean = g_red[1024 + t] * invM;
        float var  = g_red[1280 + t] * invM - mean * mean;
        float s = rsqrtf(var + EPS_) * g2[t];
        nsc[t] = s; nsh[t] = b2v[t] - mean * s; w[t] = W3[t];
    }
    __syncthreads();
    int warp = t >> 5, lane = t & 31;
    int m = blockIdx.x * 8 + warp;
    float acc = 0.0f;
    #pragma unroll
    for (int f = lane; f < 256; f += 32) {
        float v = g_o2[m * 256 + f];
        acc += fmaxf(v * nsc[f] + nsh[f], 0.0f) * w[f];
    }
    for (int o = 16; o > 0; o >>= 1)
        acc += __shfl_xor_sync(0xffffffffu, acc, o);
    if (lane == 0) out[m] = acc + b3[0];
}

// ---------------- launch ----------------
extern "C" void kernel_launch(void* const* d_in, const int* in_sizes, int n_in,
                              void* d_out, int out_size) {
    const float* data   = (const float*)d_in[0];
    const float* emb    = (const float*)d_in[1];
    const float* lin_W  = (const float*)d_in[2];
    const float* att_i  = (const float*)d_in[3];
    const float* att_j  = (const float*)d_in[4];
    const float* aem_i  = (const float*)d_in[5];
    const float* aem_j  = (const float*)d_in[6];
    // d_in[7] = gnn_bias : cancels exactly under BN
    const float* gnn_g  = (const float*)d_in[8];
    const float* gnn_b  = (const float*)d_in[9];
    const float* bno_g  = (const float*)d_in[10];
    const float* bno_b  = (const float*)d_in[11];
    const float* W1     = (const float*)d_in[12];
    // d_in[13] = b1 : cancels
    const float* bn1_g  = (const float*)d_in[14];
    const float* bn1_b  = (const float*)d_in[15];
    const float* W2     = (const float*)d_in[16];
    // d_in[17] = b2 : cancels
    const float* bn2_g  = (const float*)d_in[18];
    const float* bn2_b  = (const float*)d_in[19];
    const float* W3     = (const float*)d_in[20];
    const float* b3     = (const float*)d_in[21];
    float* out = (float*)d_out;

    const int ATTN_SMEM = (32768 + 9216 + 512) * 4;
    cudaFuncSetAttribute(k_attn2, cudaFuncAttributeMaxDynamicSharedMemorySize,
                         ATTN_SMEM);

    k_init<<<256, 256>>>(lin_W, W1, W2, emb, aem_i, aem_j);
    k_gram<<<dim3(16, 8), 256>>>(emb);
    k_sel<<<64, 256>>>();
    k_gemm<0><<<dim3(M_ / 128, 1), 256>>>(data, att_i, att_j);
    k_attn2<<<dim3(4, B_), 512, ATTN_SMEM>>>();
    k_h<<<M_ / 64, 256>>>(emb, gnn_g, gnn_b);
    k_gemm<1><<<dim3(M_ / 128, 2), 256>>>(nullptr, bno_g, bno_b);
    k_gemm<2><<<dim3(M_ / 128, 2), 256>>>(nullptr, bn1_g, bn1_b);
    k_out<<<M_ / 8, 256>>>(W3, b3, bn2_g, bn2_b, out);
}